// round 2
// baseline (speedup 1.0000x reference)
#include <cuda_runtime.h>
#include <cstdint>
#include <cstddef>

// Problem constants
#define BSZ   2
#define NSEQ  2048
#define CDIM  1024
#define HN    16
#define DH    64
#define QSCALE 0.125f            // DH^-0.5
#define ATTN_BIAS_F (-7.625f)

// Scratch: qkv as [3][B][H][N][DH], av as [B][N][H*DH]
__device__ float g_qkv[(size_t)3 * BSZ * HN * NSEQ * DH];   // 12.58M floats
__device__ float g_av[(size_t)BSZ * NSEQ * CDIM];           // 4.19M floats

#define QKV_STRIDE ((size_t)BSZ * HN * NSEQ * DH)           // 4,194,304

// ---------------------------------------------------------------------------
// Tiled SIMT fp32 GEMM: C[M,Nn] = A[M,K] @ Bw[Nn,K]^T
// 128x128 tile, BK=16, 256 threads, 8x8 per thread.
// MODE 0: plain row-major store.  MODE 1: qkv scatter + q scale.
// ---------------------------------------------------------------------------
template <int MODE>
__global__ void __launch_bounds__(256)
gemm_kernel(const float* __restrict__ A, const float* __restrict__ Bw,
            float* __restrict__ Cout, int M, int Nn, int K)
{
    extern __shared__ float sm[];
    float* As = sm;                 // [128][17]
    float* Bs = sm + 128 * 17;      // [128][17]

    const int tid = threadIdx.x;
    const int tr = tid >> 4;        // 0..15
    const int tc = tid & 15;        // 0..15
    const int row0 = blockIdx.y * 128;
    const int col0 = blockIdx.x * 128;

    float acc[8][8];
#pragma unroll
    for (int i = 0; i < 8; i++)
#pragma unroll
        for (int j = 0; j < 8; j++) acc[i][j] = 0.f;

    const int nkb = K >> 4;
    for (int kb = 0; kb < nkb; kb++) {
        // Load A tile (128 x 16) : 512 float4, 2 per thread
#pragma unroll
        for (int s = 0; s < 2; s++) {
            int ff = tid + 256 * s;
            int row = ff >> 2;
            int q = ff & 3;
            float4 v = *(const float4*)(A + (size_t)(row0 + row) * K + kb * 16 + q * 4);
            As[row * 17 + q * 4 + 0] = v.x;
            As[row * 17 + q * 4 + 1] = v.y;
            As[row * 17 + q * 4 + 2] = v.z;
            As[row * 17 + q * 4 + 3] = v.w;
        }
        // Load B tile (128 cols of W x 16)
#pragma unroll
        for (int s = 0; s < 2; s++) {
            int ff = tid + 256 * s;
            int row = ff >> 2;
            int q = ff & 3;
            float4 v = *(const float4*)(Bw + (size_t)(col0 + row) * K + kb * 16 + q * 4);
            Bs[row * 17 + q * 4 + 0] = v.x;
            Bs[row * 17 + q * 4 + 1] = v.y;
            Bs[row * 17 + q * 4 + 2] = v.z;
            Bs[row * 17 + q * 4 + 3] = v.w;
        }
        __syncthreads();

#pragma unroll
        for (int k = 0; k < 16; k++) {
            float ra[8], rb[8];
#pragma unroll
            for (int i = 0; i < 8; i++) ra[i] = As[(tr * 8 + i) * 17 + k];
#pragma unroll
            for (int j = 0; j < 8; j++) rb[j] = Bs[(tc + 16 * j) * 17 + k];
#pragma unroll
            for (int i = 0; i < 8; i++)
#pragma unroll
                for (int j = 0; j < 8; j++) acc[i][j] += ra[i] * rb[j];
        }
        __syncthreads();
    }

    if (MODE == 0) {
#pragma unroll
        for (int i = 0; i < 8; i++) {
            int r = row0 + tr * 8 + i;
#pragma unroll
            for (int j = 0; j < 8; j++) {
                int c = col0 + tc + 16 * j;
                Cout[(size_t)r * Nn + c] = acc[i][j];
            }
        }
    } else {
        // qkv scatter: column c3 of [3*C] -> (which, h, d); row r -> (b, n)
#pragma unroll
        for (int j = 0; j < 8; j++) {
            int c3 = col0 + tc + 16 * j;
            int which = c3 >> 10;
            int cc = c3 & 1023;
            int h = cc >> 6;
            int d = cc & 63;
            float mul = (which == 0) ? QSCALE : 1.0f;
#pragma unroll
            for (int i = 0; i < 8; i++) {
                int r = row0 + tr * 8 + i;
                int b = r >> 11;
                int n = r & 2047;
                size_t idx = ((((size_t)which * BSZ + b) * HN + h) * NSEQ + n) * DH + d;
                g_qkv[idx] = acc[i][j] * mul;
            }
        }
    }
}

// ---------------------------------------------------------------------------
// Fused sigmoid attention: per CTA = 128 query rows of one (b,h).
// Loops over 16 key tiles: S=QK^T -> sigmoid -> write attn_matrix + stage P
// in smem -> O += P @ V. 256 threads.
// smem: qs[128][64], ks[128][65] (reused as vs[128][64]), ps[128][132]
// ---------------------------------------------------------------------------
#define ATTN_SMEM_FLOATS (128 * 64 + 128 * 65 + 128 * 132)

__global__ void __launch_bounds__(256)
attn_kernel(float* __restrict__ attn_out,   // may be null (skip attn matrix)
            float* __restrict__ av_out2)    // may be null (extra av copy)
{
    extern __shared__ float sm[];
    float* qs = sm;                   // [128][64]
    float* ks = sm + 128 * 64;        // [128][65]  (also vs [128][64])
    float* ps = ks + 128 * 65;        // [128][132]
    float* vs = ks;

    const int tid = threadIdx.x;
    const int tr = tid >> 4;
    const int tc = tid & 15;
    const int row0 = blockIdx.x * 128;
    const int bh = blockIdx.y;
    const int b = bh >> 4;
    const int h = bh & 15;

    const size_t headoff = ((size_t)b * HN + h) * NSEQ * DH;
    const float* Qg = g_qkv + headoff + (size_t)row0 * DH;
    const float* Kg = g_qkv + QKV_STRIDE + headoff;
    const float* Vg = g_qkv + 2 * QKV_STRIDE + headoff;

    // Load Q tile (contiguous 128*64 floats)
    {
        const float4* q4 = (const float4*)Qg;
#pragma unroll
        for (int s = 0; s < 8; s++) {
            int f = tid + 256 * s;
            ((float4*)qs)[f] = q4[f];
        }
    }

    float o[8][4];
#pragma unroll
    for (int i = 0; i < 8; i++)
#pragma unroll
        for (int j = 0; j < 4; j++) o[i][j] = 0.f;

    for (int jt = 0; jt < NSEQ / 128; jt++) {
        // Load K tile into ks (width 65)
        {
            const float4* k4 = (const float4*)(Kg + (size_t)jt * 128 * DH);
#pragma unroll
            for (int s = 0; s < 8; s++) {
                int f = tid + 256 * s;
                int row = f >> 4;
                int q = f & 15;
                float4 v = k4[f];
                ks[row * 65 + q * 4 + 0] = v.x;
                ks[row * 65 + q * 4 + 1] = v.y;
                ks[row * 65 + q * 4 + 2] = v.z;
                ks[row * 65 + q * 4 + 3] = v.w;
            }
        }
        __syncthreads();

        // S = Q @ K^T (q already scaled)
        float acc[8][8];
#pragma unroll
        for (int i = 0; i < 8; i++)
#pragma unroll
            for (int j = 0; j < 8; j++) acc[i][j] = 0.f;

#pragma unroll 4
        for (int k = 0; k < 64; k++) {
            float qv[8], kv[8];
#pragma unroll
            for (int i = 0; i < 8; i++) qv[i] = qs[(tr * 8 + i) * 64 + k];
#pragma unroll
            for (int j = 0; j < 8; j++) kv[j] = ks[(tc + 16 * j) * 65 + k];
#pragma unroll
            for (int i = 0; i < 8; i++)
#pragma unroll
                for (int j = 0; j < 8; j++) acc[i][j] += qv[i] * kv[j];
        }

        // Sigmoid + store attn_matrix + stage P in smem
        float* attn_base = attn_out
            ? attn_out + ((size_t)bh * NSEQ + row0) * NSEQ + (size_t)jt * 128
            : nullptr;
#pragma unroll
        for (int i = 0; i < 8; i++) {
            int r = tr * 8 + i;
#pragma unroll
            for (int j = 0; j < 8; j++) {
                int c = tc + 16 * j;
                float x = acc[i][j] + ATTN_BIAS_F;
                float p = __fdividef(1.0f, 1.0f + __expf(-x));
                ps[r * 132 + c] = p;
                if (attn_base) attn_base[(size_t)r * NSEQ + c] = p;
            }
        }
        __syncthreads();   // ps written; ks free

        // Load V tile into vs (width 64, vectorized)
        {
            const float4* v4 = (const float4*)(Vg + (size_t)jt * 128 * DH);
#pragma unroll
            for (int s = 0; s < 8; s++) {
                int f = tid + 256 * s;
                ((float4*)vs)[f] = v4[f];
            }
        }
        __syncthreads();

        // O += P @ V : thread covers rows tr*8+i, cols tc*4..+3
#pragma unroll 2
        for (int k = 0; k < 128; k++) {
            float pv[8];
#pragma unroll
            for (int i = 0; i < 8; i++) pv[i] = ps[(tr * 8 + i) * 132 + k];
            float4 vv = *(const float4*)&vs[k * 64 + tc * 4];
#pragma unroll
            for (int i = 0; i < 8; i++) {
                o[i][0] += pv[i] * vv.x;
                o[i][1] += pv[i] * vv.y;
                o[i][2] += pv[i] * vv.z;
                o[i][3] += pv[i] * vv.w;
            }
        }
        __syncthreads();   // before next tile overwrites ks/ps
    }

    // Write O to av scratch (and optional second copy) as [B,N,H,DH]
#pragma unroll
    for (int i = 0; i < 8; i++) {
        int r = row0 + tr * 8 + i;
        size_t oidx = (((size_t)b * NSEQ + r) * HN + h) * DH + tc * 4;
        float4 v;
        v.x = o[i][0]; v.y = o[i][1]; v.z = o[i][2]; v.w = o[i][3];
        *(float4*)(g_av + oidx) = v;
        if (av_out2) *(float4*)(av_out2 + oidx) = v;
    }
}

// ---------------------------------------------------------------------------
// Launch
// ---------------------------------------------------------------------------
extern "C" void kernel_launch(void* const* d_in, const int* in_sizes, int n_in,
                              void* d_out, int out_size)
{
    const float* x     = (const float*)d_in[0];
    const float* wqkv  = (const float*)d_in[1];
    const float* wproj = (const float*)d_in[2];
    float* out = (float*)d_out;

    const size_t SZ_ATTN = (size_t)BSZ * HN * NSEQ * NSEQ;   // 134,217,728
    const size_t SZ_AV   = (size_t)BSZ * NSEQ * CDIM;        //   4,194,304
    const bool full = ((size_t)out_size >= SZ_ATTN + 2 * SZ_AV);

    const int gemm_smem = 2 * 128 * 17 * sizeof(float);      // 17408 B
    const int attn_smem = ATTN_SMEM_FLOATS * sizeof(float);  // 133632 B

    // Resolve the device address of the g_av scratch symbol ONCE.
    // (Passing the __device__ symbol directly from host code passes the
    //  host shadow address -> kernel fault. This was the Round-1 bug.)
    static float* g_av_dev = nullptr;
    static bool attr_done = false;
    if (!attr_done) {
        cudaFuncSetAttribute(attn_kernel,
                             cudaFuncAttributeMaxDynamicSharedMemorySize, attn_smem);
        cudaGetSymbolAddress((void**)&g_av_dev, g_av);
        attr_done = true;
    }

    // 1) QKV projection: [4096,1024] @ [3072,1024]^T, scatter to g_qkv
    gemm_kernel<1><<<dim3(3 * CDIM / 128, (BSZ * NSEQ) / 128), 256, gemm_smem>>>(
        x, wqkv, nullptr, BSZ * NSEQ, 3 * CDIM, CDIM);

    // 2) Fused sigmoid attention
    float* attn_dst = full ? out : nullptr;
    float* av_dst2  = full ? out + SZ_ATTN : nullptr;
    attn_kernel<<<dim3(NSEQ / 128, BSZ * HN), 256, attn_smem>>>(attn_dst, av_dst2);

    // 3) Output projection: av [4096,1024] @ [1024,1024]^T
    // Read av from the output buffer when available (same data, already
    // written by attn_kernel), else from the resolved scratch pointer.
    const float* av_src = full ? (const float*)(out + SZ_ATTN)
                               : (const float*)g_av_dev;
    float* proj_dst = full ? out + SZ_ATTN + SZ_AV : out;
    gemm_kernel<0><<<dim3(CDIM / 128, (BSZ * NSEQ) / 128), 256, gemm_smem>>>(
        av_src, wproj, proj_dst, BSZ * NSEQ, CDIM, CDIM);
}

// round 5
// speedup vs baseline: 2.1093x; 2.1093x over previous
#include <cuda_runtime.h>
#include <cuda_bf16.h>
#include <cstdint>
#include <cstddef>

// Problem constants
#define BSZ   2
#define NSEQ  2048
#define CDIM  1024
#define HN    16
#define DH    64
#define QSCALE 0.125f            // DH^-0.5
#define ATTN_BIAS_F (-7.625f)

// Scratch: qkv as [3][B][H][N][DH], av as [B][N][H*DH]
__device__ float g_qkv[(size_t)3 * BSZ * HN * NSEQ * DH];
__device__ float g_av[(size_t)BSZ * NSEQ * CDIM];

#define QKV_STRIDE ((size_t)BSZ * HN * NSEQ * DH)

// ---------------------------------------------------------------------------
// mma.sync helpers (arch-portable HMMA path; tcgen05 PTX is rejected by this
// harness's ptxas target, so tensor cores are reached via m16n8k16 bf16).
// ---------------------------------------------------------------------------
__device__ __forceinline__ void mma_bf16(float c[4], const uint32_t a[4],
                                         const uint32_t b[2]) {
    asm volatile(
        "mma.sync.aligned.m16n8k16.row.col.f32.bf16.bf16.f32 "
        "{%0,%1,%2,%3}, {%4,%5,%6,%7}, {%8,%9}, {%0,%1,%2,%3};\n"
        : "+f"(c[0]), "+f"(c[1]), "+f"(c[2]), "+f"(c[3])
        : "r"(a[0]), "r"(a[1]), "r"(a[2]), "r"(a[3]), "r"(b[0]), "r"(b[1]));
}

// A-fragment (16x16) from bf16 smem, row-major, stride S elements.
__device__ __forceinline__ void lda_frag(uint32_t a[4], const __nv_bfloat16* base,
                                         int row0, int k0, int S, int grp, int qd) {
    const __nv_bfloat16* p = base + (size_t)(row0 + grp) * S + k0 + qd * 2;
    a[0] = *(const uint32_t*)p;
    a[1] = *(const uint32_t*)(p + 8 * S);
    a[2] = *(const uint32_t*)(p + 8);
    a[3] = *(const uint32_t*)(p + 8 * S + 8);
}
// B-fragment (16x8, col-major in k) from bf16 smem laid out [n][k] row-major.
__device__ __forceinline__ void ldb_frag(uint32_t b[2], const __nv_bfloat16* base,
                                         int n0, int k0, int S, int grp, int qd) {
    const __nv_bfloat16* p = base + (size_t)(n0 + grp) * S + k0 + qd * 2;
    b[0] = *(const uint32_t*)p;
    b[1] = *(const uint32_t*)(p + 8);
}

__device__ __forceinline__ void splitf(float v, __nv_bfloat16& h, __nv_bfloat16& l) {
    h = __float2bfloat16_rn(v);
    l = __float2bfloat16_rn(v - __bfloat162float(h));
}
__device__ __forceinline__ uint32_t b2u(__nv_bfloat16 a, __nv_bfloat16 b) {
    __nv_bfloat162 t(a, b);
    return *reinterpret_cast<uint32_t*>(&t);
}
// split a float4 into hi/lo packed as uint2 (4 bf16 each)
__device__ __forceinline__ void split4(float4 v, uint2& hi, uint2& lo) {
    __nv_bfloat16 h0, h1, h2, h3, l0, l1, l2, l3;
    splitf(v.x, h0, l0); splitf(v.y, h1, l1);
    splitf(v.z, h2, l2); splitf(v.w, h3, l3);
    hi.x = b2u(h0, h1); hi.y = b2u(h2, h3);
    lo.x = b2u(l0, l1); lo.y = b2u(l2, l3);
}

// ---------------------------------------------------------------------------
// Split-bf16 HMMA GEMM: C[M,Nn] = A[M,K] @ Bw[Nn,K]^T  (fp32 in/out)
// 128x128 CTA tile, 256 threads (8 warps, 2x4), K-chunk 64.
// MODE 0: row-major store. MODE 1: qkv scatter + q scale.
// smem: Ah/Al/Bh/Bl each [128][72] bf16 -> 73728 B
// ---------------------------------------------------------------------------
#define GS 72
#define TCGEMM_SMEM (4 * 128 * GS * 2)

template <int MODE>
__global__ void __launch_bounds__(256, 1)
tc_gemm(const float* __restrict__ A, const float* __restrict__ Bw,
        float* __restrict__ Cout, int M, int Nn, int K)
{
    extern __shared__ __nv_bfloat16 smg[];
    __nv_bfloat16* Ah = smg;
    __nv_bfloat16* Al = Ah + 128 * GS;
    __nv_bfloat16* Bh = Al + 128 * GS;
    __nv_bfloat16* Bl = Bh + 128 * GS;

    const int tid = threadIdx.x;
    const int wid = tid >> 5, lane = tid & 31;
    const int grp = lane >> 2, qd = lane & 3;
    const int wm = wid >> 2, wn = wid & 3;     // 2 x 4 warp grid
    const int row0 = blockIdx.y * 128, col0 = blockIdx.x * 128;

    float acc[4][4][4];
#pragma unroll
    for (int i = 0; i < 4; i++)
#pragma unroll
        for (int j = 0; j < 4; j++)
#pragma unroll
            for (int t = 0; t < 4; t++) acc[i][j][t] = 0.f;

    const int nchunks = K >> 6;
    for (int kb = 0; kb < nchunks; kb++) {
        // stage + split A and B 128x64 chunks
#pragma unroll
        for (int s = 0; s < 8; s++) {
            int f = tid + 256 * s;
            int row = f >> 4, q = f & 15;
            float4 va = *(const float4*)(A + (size_t)(row0 + row) * K + kb * 64 + q * 4);
            uint2 hi, lo; split4(va, hi, lo);
            *(uint2*)(Ah + row * GS + q * 4) = hi;
            *(uint2*)(Al + row * GS + q * 4) = lo;
            float4 vb = *(const float4*)(Bw + (size_t)(col0 + row) * K + kb * 64 + q * 4);
            split4(vb, hi, lo);
            *(uint2*)(Bh + row * GS + q * 4) = hi;
            *(uint2*)(Bl + row * GS + q * 4) = lo;
        }
        __syncthreads();

#pragma unroll
        for (int ks = 0; ks < 4; ks++) {
            const int k0 = ks * 16;
            uint32_t bh[4][2], bl[4][2];
#pragma unroll
            for (int nt = 0; nt < 4; nt++) {
                ldb_frag(bh[nt], Bh, wn * 32 + nt * 8, k0, GS, grp, qd);
                ldb_frag(bl[nt], Bl, wn * 32 + nt * 8, k0, GS, grp, qd);
            }
#pragma unroll
            for (int mt = 0; mt < 4; mt++) {
                uint32_t ah[4], al[4];
                lda_frag(ah, Ah, wm * 64 + mt * 16, k0, GS, grp, qd);
                lda_frag(al, Al, wm * 64 + mt * 16, k0, GS, grp, qd);
#pragma unroll
                for (int nt = 0; nt < 4; nt++) {
                    mma_bf16(acc[mt][nt], ah, bh[nt]);
                    mma_bf16(acc[mt][nt], ah, bl[nt]);
                    mma_bf16(acc[mt][nt], al, bh[nt]);
                }
            }
        }
        __syncthreads();
    }

    // epilogue
#pragma unroll
    for (int mt = 0; mt < 4; mt++) {
        int r = row0 + wm * 64 + mt * 16 + grp;
#pragma unroll
        for (int nt = 0; nt < 4; nt++) {
            int cl = wn * 32 + nt * 8 + qd * 2;
            float* a4 = acc[mt][nt];
            if (MODE == 0) {
                float2 v0 = {a4[0], a4[1]};
                float2 v1 = {a4[2], a4[3]};
                *(float2*)(Cout + (size_t)r * Nn + col0 + cl) = v0;
                *(float2*)(Cout + (size_t)(r + 8) * Nn + col0 + cl) = v1;
            } else {
                int c3 = col0 + cl;
                int which = c3 >> 10;
                int cc = c3 & 1023;
                int h = cc >> 6;
                int d = cc & 63;
                float mul = (which == 0) ? QSCALE : 1.0f;
                int b = r >> 11, n = r & 2047;
                size_t base = ((((size_t)which * BSZ + b) * HN + h) * NSEQ + n) * DH + d;
                float2 v0 = {a4[0] * mul, a4[1] * mul};
                float2 v1 = {a4[2] * mul, a4[3] * mul};
                *(float2*)(g_qkv + base) = v0;
                *(float2*)(g_qkv + base + 8 * (size_t)DH) = v1;  // n+8 row
            }
        }
    }
}

// ---------------------------------------------------------------------------
// Fused sigmoid attention with HMMA.
// CTA = 128 q-rows of one (b,h), 256 threads.
// S phase: 2x4 warp grid over S[128][128]; PV phase: 4x2 grid over O[128][64].
// smem (bf16): qh/ql[128][72], kh/kl[128][72], vh/vl[64][136], ph/pl[128][136]
// ---------------------------------------------------------------------------
#define QKS 72
#define VPS 136
#define ATTN_SMEM_BYTES ((4 * 128 * QKS + 2 * 64 * VPS + 2 * 128 * VPS) * 2)

__global__ void __launch_bounds__(256, 1)
attn_kernel(float* __restrict__ attn_out, float* __restrict__ av_out2)
{
    extern __shared__ __nv_bfloat16 sma[];
    __nv_bfloat16* qh = sma;
    __nv_bfloat16* ql = qh + 128 * QKS;
    __nv_bfloat16* kh = ql + 128 * QKS;
    __nv_bfloat16* kl = kh + 128 * QKS;
    __nv_bfloat16* vh = kl + 128 * QKS;
    __nv_bfloat16* vl = vh + 64 * VPS;
    __nv_bfloat16* ph = vl + 64 * VPS;
    __nv_bfloat16* pl = ph + 128 * VPS;

    const int tid = threadIdx.x;
    const int wid = tid >> 5, lane = tid & 31;
    const int grp = lane >> 2, qd = lane & 3;
    const int wm = wid >> 2, wn = wid & 3;     // S-phase 2x4
    const int wm2 = wid >> 1, wn2 = wid & 1;   // PV-phase 4x2
    const int row0 = blockIdx.x * 128;
    const int bhid = blockIdx.y;
    const int b = bhid >> 4, h = bhid & 15;

    const size_t headoff = ((size_t)b * HN + h) * NSEQ * DH;
    const float* Qg = g_qkv + headoff + (size_t)row0 * DH;
    const float* Kg = g_qkv + QKV_STRIDE + headoff;
    const float* Vg = g_qkv + 2 * QKV_STRIDE + headoff;

    // Load + split Q (128x64)
#pragma unroll
    for (int s = 0; s < 8; s++) {
        int f = tid + 256 * s;
        int row = f >> 4, q = f & 15;
        float4 v = ((const float4*)Qg)[f];
        uint2 hi, lo; split4(v, hi, lo);
        *(uint2*)(qh + row * QKS + q * 4) = hi;
        *(uint2*)(ql + row * QKS + q * 4) = lo;
    }

    float oacc[2][4][4];
#pragma unroll
    for (int i = 0; i < 2; i++)
#pragma unroll
        for (int j = 0; j < 4; j++)
#pragma unroll
            for (int t = 0; t < 4; t++) oacc[i][j][t] = 0.f;

    __syncthreads();

    for (int jt = 0; jt < NSEQ / 128; jt++) {
        // Load + split K tile (128x64)
#pragma unroll
        for (int s = 0; s < 8; s++) {
            int f = tid + 256 * s;
            int row = f >> 4, q = f & 15;
            float4 v = ((const float4*)(Kg + (size_t)jt * 128 * DH))[f];
            uint2 hi, lo; split4(v, hi, lo);
            *(uint2*)(kh + row * QKS + q * 4) = hi;
            *(uint2*)(kl + row * QKS + q * 4) = lo;
        }
        // Load + split + transpose V tile -> vs[d][key]
#pragma unroll
        for (int s = 0; s < 8; s++) {
            int f = tid + 256 * s;
            int key = f >> 4, q = f & 15;
            float4 v = ((const float4*)(Vg + (size_t)jt * 128 * DH))[f];
            int d0 = q * 4;
            __nv_bfloat16 hb, lb;
            splitf(v.x, hb, lb); vh[(d0 + 0) * VPS + key] = hb; vl[(d0 + 0) * VPS + key] = lb;
            splitf(v.y, hb, lb); vh[(d0 + 1) * VPS + key] = hb; vl[(d0 + 1) * VPS + key] = lb;
            splitf(v.z, hb, lb); vh[(d0 + 2) * VPS + key] = hb; vl[(d0 + 2) * VPS + key] = lb;
            splitf(v.w, hb, lb); vh[(d0 + 3) * VPS + key] = hb; vl[(d0 + 3) * VPS + key] = lb;
        }
        __syncthreads();

        // ---- S = Q @ K^T ----
        float sacc[4][4][4];
#pragma unroll
        for (int i = 0; i < 4; i++)
#pragma unroll
            for (int j = 0; j < 4; j++)
#pragma unroll
                for (int t = 0; t < 4; t++) sacc[i][j][t] = 0.f;

#pragma unroll
        for (int ks = 0; ks < 4; ks++) {
            const int k0 = ks * 16;
            uint32_t bh_[4][2], bl_[4][2];
#pragma unroll
            for (int nt = 0; nt < 4; nt++) {
                ldb_frag(bh_[nt], kh, wn * 32 + nt * 8, k0, QKS, grp, qd);
                ldb_frag(bl_[nt], kl, wn * 32 + nt * 8, k0, QKS, grp, qd);
            }
#pragma unroll
            for (int mt = 0; mt < 4; mt++) {
                uint32_t ah[4], al[4];
                lda_frag(ah, qh, wm * 64 + mt * 16, k0, QKS, grp, qd);
                lda_frag(al, ql, wm * 64 + mt * 16, k0, QKS, grp, qd);
#pragma unroll
                for (int nt = 0; nt < 4; nt++) {
                    mma_bf16(sacc[mt][nt], ah, bh_[nt]);
                    mma_bf16(sacc[mt][nt], ah, bl_[nt]);
                    mma_bf16(sacc[mt][nt], al, bh_[nt]);
                }
            }
        }

        // ---- sigmoid + attn_matrix store + stage split P ----
        float* ab = attn_out
            ? attn_out + ((size_t)bhid * NSEQ + row0) * NSEQ + (size_t)jt * 128
            : nullptr;
#pragma unroll
        for (int mt = 0; mt < 4; mt++) {
            int r1 = wm * 64 + mt * 16 + grp;
#pragma unroll
            for (int nt = 0; nt < 4; nt++) {
                int c = wn * 32 + nt * 8 + qd * 2;
                float* a4 = sacc[mt][nt];
                float p0 = __fdividef(1.f, 1.f + __expf(-(a4[0] + ATTN_BIAS_F)));
                float p1 = __fdividef(1.f, 1.f + __expf(-(a4[1] + ATTN_BIAS_F)));
                float p2 = __fdividef(1.f, 1.f + __expf(-(a4[2] + ATTN_BIAS_F)));
                float p3 = __fdividef(1.f, 1.f + __expf(-(a4[3] + ATTN_BIAS_F)));
                if (ab) {
                    float2 v0 = {p0, p1}, v1 = {p2, p3};
                    *(float2*)(ab + (size_t)r1 * NSEQ + c) = v0;
                    *(float2*)(ab + (size_t)(r1 + 8) * NSEQ + c) = v1;
                }
                __nv_bfloat16 h0, h1, h2, h3, l0, l1, l2, l3;
                splitf(p0, h0, l0); splitf(p1, h1, l1);
                splitf(p2, h2, l2); splitf(p3, h3, l3);
                *(uint32_t*)(ph + r1 * VPS + c) = b2u(h0, h1);
                *(uint32_t*)(pl + r1 * VPS + c) = b2u(l0, l1);
                *(uint32_t*)(ph + (r1 + 8) * VPS + c) = b2u(h2, h3);
                *(uint32_t*)(pl + (r1 + 8) * VPS + c) = b2u(l2, l3);
            }
        }
        __syncthreads();

        // ---- O += P @ V ----
#pragma unroll
        for (int ks = 0; ks < 8; ks++) {
            const int k0 = ks * 16;
            uint32_t vbh[4][2], vbl[4][2];
#pragma unroll
            for (int nt = 0; nt < 4; nt++) {
                ldb_frag(vbh[nt], vh, wn2 * 32 + nt * 8, k0, VPS, grp, qd);
                ldb_frag(vbl[nt], vl, wn2 * 32 + nt * 8, k0, VPS, grp, qd);
            }
#pragma unroll
            for (int mt = 0; mt < 2; mt++) {
                uint32_t pah[4], pal[4];
                lda_frag(pah, ph, wm2 * 32 + mt * 16, k0, VPS, grp, qd);
                lda_frag(pal, pl, wm2 * 32 + mt * 16, k0, VPS, grp, qd);
#pragma unroll
                for (int nt = 0; nt < 4; nt++) {
                    mma_bf16(oacc[mt][nt], pah, vbh[nt]);
                    mma_bf16(oacc[mt][nt], pah, vbl[nt]);
                    mma_bf16(oacc[mt][nt], pal, vbh[nt]);
                }
            }
        }
        __syncthreads();   // protect k/v/p smem before next tile
    }

    // ---- epilogue: O -> g_av [B,N,H*DH] (+ optional copy to out) ----
#pragma unroll
    for (int mt = 0; mt < 2; mt++) {
        int r = row0 + wm2 * 32 + mt * 16 + grp;
#pragma unroll
        for (int nt = 0; nt < 4; nt++) {
            int d = wn2 * 32 + nt * 8 + qd * 2;
            float* a4 = oacc[mt][nt];
            size_t base = (((size_t)b * NSEQ + r) * HN + h) * DH + d;
            float2 v0 = {a4[0], a4[1]}, v1 = {a4[2], a4[3]};
            *(float2*)(g_av + base) = v0;
            *(float2*)(g_av + base + 8 * (size_t)CDIM) = v1;
            if (av_out2) {
                *(float2*)(av_out2 + base) = v0;
                *(float2*)(av_out2 + base + 8 * (size_t)CDIM) = v1;
            }
        }
    }
}

// ---------------------------------------------------------------------------
// Launch
// ---------------------------------------------------------------------------
extern "C" void kernel_launch(void* const* d_in, const int* in_sizes, int n_in,
                              void* d_out, int out_size)
{
    const float* x     = (const float*)d_in[0];
    const float* wqkv  = (const float*)d_in[1];
    const float* wproj = (const float*)d_in[2];
    float* out = (float*)d_out;

    const size_t SZ_ATTN = (size_t)BSZ * HN * NSEQ * NSEQ;
    const size_t SZ_AV   = (size_t)BSZ * NSEQ * CDIM;
    const bool full = ((size_t)out_size >= SZ_ATTN + 2 * SZ_AV);

    static float* g_av_dev = nullptr;
    static bool attr_done = false;
    if (!attr_done) {
        cudaFuncSetAttribute(attn_kernel,
                             cudaFuncAttributeMaxDynamicSharedMemorySize, ATTN_SMEM_BYTES);
        cudaFuncSetAttribute(tc_gemm<0>,
                             cudaFuncAttributeMaxDynamicSharedMemorySize, TCGEMM_SMEM);
        cudaFuncSetAttribute(tc_gemm<1>,
                             cudaFuncAttributeMaxDynamicSharedMemorySize, TCGEMM_SMEM);
        cudaGetSymbolAddress((void**)&g_av_dev, g_av);
        attr_done = true;
    }

    // 1) QKV projection -> g_qkv scatter (q pre-scaled)
    tc_gemm<1><<<dim3(3 * CDIM / 128, (BSZ * NSEQ) / 128), 256, TCGEMM_SMEM>>>(
        x, wqkv, nullptr, BSZ * NSEQ, 3 * CDIM, CDIM);

    // 2) Fused sigmoid attention
    float* attn_dst = full ? out : nullptr;
    float* av_dst2  = full ? out + SZ_ATTN : nullptr;
    attn_kernel<<<dim3(NSEQ / 128, BSZ * HN), 256, ATTN_SMEM_BYTES>>>(attn_dst, av_dst2);

    // 3) Output projection
    const float* av_src = full ? (const float*)(out + SZ_ATTN)
                               : (const float*)g_av_dev;
    float* proj_dst = full ? out + SZ_ATTN + SZ_AV : out;
    tc_gemm<0><<<dim3(CDIM / 128, (BSZ * NSEQ) / 128), 256, TCGEMM_SMEM>>>(
        av_src, wproj, proj_dst, BSZ * NSEQ, CDIM, CDIM);
}

// round 6
// speedup vs baseline: 2.1123x; 1.0014x over previous
#include <cuda_runtime.h>
#include <cuda_bf16.h>
#include <cstdint>
#include <cstddef>

// Problem constants
#define BSZ   2
#define NSEQ  2048
#define CDIM  1024
#define HN    16
#define DH    64
#define QSCALE 0.125f            // DH^-0.5
#define ATTN_BIAS_F (-7.625f)

// Scratch: qkv as [3][B][H][N][DH], av as [B][N][H*DH]
__device__ float g_qkv[(size_t)3 * BSZ * HN * NSEQ * DH];
__device__ float g_av[(size_t)BSZ * NSEQ * CDIM];

#define QKV_STRIDE ((size_t)BSZ * HN * NSEQ * DH)

// ---------------------------------------------------------------------------
// mma.sync helpers (arch-portable HMMA path; tcgen05 PTX is rejected by this
// harness's ptxas target, so tensor cores are reached via m16n8k16 bf16).
// ---------------------------------------------------------------------------
__device__ __forceinline__ void mma_bf16(float c[4], const uint32_t a[4],
                                         const uint32_t b[2]) {
    asm volatile(
        "mma.sync.aligned.m16n8k16.row.col.f32.bf16.bf16.f32 "
        "{%0,%1,%2,%3}, {%4,%5,%6,%7}, {%8,%9}, {%0,%1,%2,%3};\n"
        : "+f"(c[0]), "+f"(c[1]), "+f"(c[2]), "+f"(c[3])
        : "r"(a[0]), "r"(a[1]), "r"(a[2]), "r"(a[3]), "r"(b[0]), "r"(b[1]));
}

// A-fragment (16x16) from bf16 smem, row-major, stride S elements.
__device__ __forceinline__ void lda_frag(uint32_t a[4], const __nv_bfloat16* base,
                                         int row0, int k0, int S, int grp, int qd) {
    const __nv_bfloat16* p = base + (size_t)(row0 + grp) * S + k0 + qd * 2;
    a[0] = *(const uint32_t*)p;
    a[1] = *(const uint32_t*)(p + 8 * S);
    a[2] = *(const uint32_t*)(p + 8);
    a[3] = *(const uint32_t*)(p + 8 * S + 8);
}
// B-fragment (16x8, col-major in k) from bf16 smem laid out [n][k] row-major.
__device__ __forceinline__ void ldb_frag(uint32_t b[2], const __nv_bfloat16* base,
                                         int n0, int k0, int S, int grp, int qd) {
    const __nv_bfloat16* p = base + (size_t)(n0 + grp) * S + k0 + qd * 2;
    b[0] = *(const uint32_t*)p;
    b[1] = *(const uint32_t*)(p + 8);
}

__device__ __forceinline__ void splitf(float v, __nv_bfloat16& h, __nv_bfloat16& l) {
    h = __float2bfloat16_rn(v);
    l = __float2bfloat16_rn(v - __bfloat162float(h));
}
__device__ __forceinline__ uint32_t b2u(__nv_bfloat16 a, __nv_bfloat16 b) {
    __nv_bfloat162 t(a, b);
    return *reinterpret_cast<uint32_t*>(&t);
}
// split a float4 into hi/lo packed as uint2 (4 bf16 each)
__device__ __forceinline__ void split4(float4 v, uint2& hi, uint2& lo) {
    __nv_bfloat16 h0, h1, h2, h3, l0, l1, l2, l3;
    splitf(v.x, h0, l0); splitf(v.y, h1, l1);
    splitf(v.z, h2, l2); splitf(v.w, h3, l3);
    hi.x = b2u(h0, h1); hi.y = b2u(h2, h3);
    lo.x = b2u(l0, l1); lo.y = b2u(l2, l3);
}

// ---------------------------------------------------------------------------
// Split-bf16 HMMA GEMM: C[M,Nn] = A[M,K] @ Bw[Nn,K]^T  (fp32 in/out)
// 128x128 CTA tile, 256 threads (8 warps, 2x4), K-chunk 64.
// MODE 0: row-major store. MODE 1: qkv scatter + q scale.
// smem: Ah/Al/Bh/Bl each [128][72] bf16 -> 73728 B
// ---------------------------------------------------------------------------
#define GS 72
#define TCGEMM_SMEM (4 * 128 * GS * 2)

template <int MODE>
__global__ void __launch_bounds__(256, 1)
tc_gemm(const float* __restrict__ A, const float* __restrict__ Bw,
        float* __restrict__ Cout, int M, int Nn, int K)
{
    extern __shared__ __nv_bfloat16 smg[];
    __nv_bfloat16* Ah = smg;
    __nv_bfloat16* Al = Ah + 128 * GS;
    __nv_bfloat16* Bh = Al + 128 * GS;
    __nv_bfloat16* Bl = Bh + 128 * GS;

    const int tid = threadIdx.x;
    const int wid = tid >> 5, lane = tid & 31;
    const int grp = lane >> 2, qd = lane & 3;
    const int wm = wid >> 2, wn = wid & 3;     // 2 x 4 warp grid
    const int row0 = blockIdx.y * 128, col0 = blockIdx.x * 128;

    float acc[4][4][4];
#pragma unroll
    for (int i = 0; i < 4; i++)
#pragma unroll
        for (int j = 0; j < 4; j++)
#pragma unroll
            for (int t = 0; t < 4; t++) acc[i][j][t] = 0.f;

    const int nchunks = K >> 6;
    for (int kb = 0; kb < nchunks; kb++) {
        // stage + split A and B 128x64 chunks
#pragma unroll
        for (int s = 0; s < 8; s++) {
            int f = tid + 256 * s;
            int row = f >> 4, q = f & 15;
            float4 va = *(const float4*)(A + (size_t)(row0 + row) * K + kb * 64 + q * 4);
            uint2 hi, lo; split4(va, hi, lo);
            *(uint2*)(Ah + row * GS + q * 4) = hi;
            *(uint2*)(Al + row * GS + q * 4) = lo;
            float4 vb = *(const float4*)(Bw + (size_t)(col0 + row) * K + kb * 64 + q * 4);
            split4(vb, hi, lo);
            *(uint2*)(Bh + row * GS + q * 4) = hi;
            *(uint2*)(Bl + row * GS + q * 4) = lo;
        }
        __syncthreads();

#pragma unroll
        for (int ks = 0; ks < 4; ks++) {
            const int k0 = ks * 16;
            uint32_t bh[4][2], bl[4][2];
#pragma unroll
            for (int nt = 0; nt < 4; nt++) {
                ldb_frag(bh[nt], Bh, wn * 32 + nt * 8, k0, GS, grp, qd);
                ldb_frag(bl[nt], Bl, wn * 32 + nt * 8, k0, GS, grp, qd);
            }
#pragma unroll
            for (int mt = 0; mt < 4; mt++) {
                uint32_t ah[4], al[4];
                lda_frag(ah, Ah, wm * 64 + mt * 16, k0, GS, grp, qd);
                lda_frag(al, Al, wm * 64 + mt * 16, k0, GS, grp, qd);
#pragma unroll
                for (int nt = 0; nt < 4; nt++) {
                    mma_bf16(acc[mt][nt], ah, bh[nt]);
                    mma_bf16(acc[mt][nt], ah, bl[nt]);
                    mma_bf16(acc[mt][nt], al, bh[nt]);
                }
            }
        }
        __syncthreads();
    }

    // epilogue
#pragma unroll
    for (int mt = 0; mt < 4; mt++) {
        int r = row0 + wm * 64 + mt * 16 + grp;
#pragma unroll
        for (int nt = 0; nt < 4; nt++) {
            int cl = wn * 32 + nt * 8 + qd * 2;
            float* a4 = acc[mt][nt];
            if (MODE == 0) {
                float2 v0 = {a4[0], a4[1]};
                float2 v1 = {a4[2], a4[3]};
                *(float2*)(Cout + (size_t)r * Nn + col0 + cl) = v0;
                *(float2*)(Cout + (size_t)(r + 8) * Nn + col0 + cl) = v1;
            } else {
                int c3 = col0 + cl;
                int which = c3 >> 10;
                int cc = c3 & 1023;
                int h = cc >> 6;
                int d = cc & 63;
                float mul = (which == 0) ? QSCALE : 1.0f;
                int b = r >> 11, n = r & 2047;
                size_t base = ((((size_t)which * BSZ + b) * HN + h) * NSEQ + n) * DH + d;
                float2 v0 = {a4[0] * mul, a4[1] * mul};
                float2 v1 = {a4[2] * mul, a4[3] * mul};
                *(float2*)(g_qkv + base) = v0;
                *(float2*)(g_qkv + base + 8 * (size_t)DH) = v1;  // n+8 row
            }
        }
    }
}

// ---------------------------------------------------------------------------
// Fused sigmoid attention with HMMA.
// CTA = 128 q-rows of one (b,h), 256 threads.
// S phase: 2x4 warp grid over S[128][128]; PV phase: 4x2 grid over O[128][64].
// smem (bf16): qh/ql[128][72], kh/kl[128][72], vh/vl[64][136], ph/pl[128][136]
// ---------------------------------------------------------------------------
#define QKS 72
#define VPS 136
#define ATTN_SMEM_BYTES ((4 * 128 * QKS + 2 * 64 * VPS + 2 * 128 * VPS) * 2)

__global__ void __launch_bounds__(256, 1)
attn_kernel(float* __restrict__ attn_out, float* __restrict__ av_out2)
{
    extern __shared__ __nv_bfloat16 sma[];
    __nv_bfloat16* qh = sma;
    __nv_bfloat16* ql = qh + 128 * QKS;
    __nv_bfloat16* kh = ql + 128 * QKS;
    __nv_bfloat16* kl = kh + 128 * QKS;
    __nv_bfloat16* vh = kl + 128 * QKS;
    __nv_bfloat16* vl = vh + 64 * VPS;
    __nv_bfloat16* ph = vl + 64 * VPS;
    __nv_bfloat16* pl = ph + 128 * VPS;

    const int tid = threadIdx.x;
    const int wid = tid >> 5, lane = tid & 31;
    const int grp = lane >> 2, qd = lane & 3;
    const int wm = wid >> 2, wn = wid & 3;     // S-phase 2x4
    const int wm2 = wid >> 1, wn2 = wid & 1;   // PV-phase 4x2
    const int row0 = blockIdx.x * 128;
    const int bhid = blockIdx.y;
    const int b = bhid >> 4, h = bhid & 15;

    const size_t headoff = ((size_t)b * HN + h) * NSEQ * DH;
    const float* Qg = g_qkv + headoff + (size_t)row0 * DH;
    const float* Kg = g_qkv + QKV_STRIDE + headoff;
    const float* Vg = g_qkv + 2 * QKV_STRIDE + headoff;

    // Load + split Q (128x64)
#pragma unroll
    for (int s = 0; s < 8; s++) {
        int f = tid + 256 * s;
        int row = f >> 4, q = f & 15;
        float4 v = ((const float4*)Qg)[f];
        uint2 hi, lo; split4(v, hi, lo);
        *(uint2*)(qh + row * QKS + q * 4) = hi;
        *(uint2*)(ql + row * QKS + q * 4) = lo;
    }

    float oacc[2][4][4];
#pragma unroll
    for (int i = 0; i < 2; i++)
#pragma unroll
        for (int j = 0; j < 4; j++)
#pragma unroll
            for (int t = 0; t < 4; t++) oacc[i][j][t] = 0.f;

    __syncthreads();

    for (int jt = 0; jt < NSEQ / 128; jt++) {
        // Load + split K tile (128x64)
#pragma unroll
        for (int s = 0; s < 8; s++) {
            int f = tid + 256 * s;
            int row = f >> 4, q = f & 15;
            float4 v = ((const float4*)(Kg + (size_t)jt * 128 * DH))[f];
            uint2 hi, lo; split4(v, hi, lo);
            *(uint2*)(kh + row * QKS + q * 4) = hi;
            *(uint2*)(kl + row * QKS + q * 4) = lo;
        }
        // Load + split + transpose V tile -> vs[d][key]
#pragma unroll
        for (int s = 0; s < 8; s++) {
            int f = tid + 256 * s;
            int key = f >> 4, q = f & 15;
            float4 v = ((const float4*)(Vg + (size_t)jt * 128 * DH))[f];
            int d0 = q * 4;
            __nv_bfloat16 hb, lb;
            splitf(v.x, hb, lb); vh[(d0 + 0) * VPS + key] = hb; vl[(d0 + 0) * VPS + key] = lb;
            splitf(v.y, hb, lb); vh[(d0 + 1) * VPS + key] = hb; vl[(d0 + 1) * VPS + key] = lb;
            splitf(v.z, hb, lb); vh[(d0 + 2) * VPS + key] = hb; vl[(d0 + 2) * VPS + key] = lb;
            splitf(v.w, hb, lb); vh[(d0 + 3) * VPS + key] = hb; vl[(d0 + 3) * VPS + key] = lb;
        }
        __syncthreads();

        // ---- S = Q @ K^T ----
        float sacc[4][4][4];
#pragma unroll
        for (int i = 0; i < 4; i++)
#pragma unroll
            for (int j = 0; j < 4; j++)
#pragma unroll
                for (int t = 0; t < 4; t++) sacc[i][j][t] = 0.f;

#pragma unroll
        for (int ks = 0; ks < 4; ks++) {
            const int k0 = ks * 16;
            uint32_t bh_[4][2], bl_[4][2];
#pragma unroll
            for (int nt = 0; nt < 4; nt++) {
                ldb_frag(bh_[nt], kh, wn * 32 + nt * 8, k0, QKS, grp, qd);
                ldb_frag(bl_[nt], kl, wn * 32 + nt * 8, k0, QKS, grp, qd);
            }
#pragma unroll
            for (int mt = 0; mt < 4; mt++) {
                uint32_t ah[4], al[4];
                lda_frag(ah, qh, wm * 64 + mt * 16, k0, QKS, grp, qd);
                lda_frag(al, ql, wm * 64 + mt * 16, k0, QKS, grp, qd);
#pragma unroll
                for (int nt = 0; nt < 4; nt++) {
                    mma_bf16(sacc[mt][nt], ah, bh_[nt]);
                    mma_bf16(sacc[mt][nt], ah, bl_[nt]);
                    mma_bf16(sacc[mt][nt], al, bh_[nt]);
                }
            }
        }

        // ---- sigmoid + attn_matrix store + stage split P ----
        float* ab = attn_out
            ? attn_out + ((size_t)bhid * NSEQ + row0) * NSEQ + (size_t)jt * 128
            : nullptr;
#pragma unroll
        for (int mt = 0; mt < 4; mt++) {
            int r1 = wm * 64 + mt * 16 + grp;
#pragma unroll
            for (int nt = 0; nt < 4; nt++) {
                int c = wn * 32 + nt * 8 + qd * 2;
                float* a4 = sacc[mt][nt];
                float p0 = __fdividef(1.f, 1.f + __expf(-(a4[0] + ATTN_BIAS_F)));
                float p1 = __fdividef(1.f, 1.f + __expf(-(a4[1] + ATTN_BIAS_F)));
                float p2 = __fdividef(1.f, 1.f + __expf(-(a4[2] + ATTN_BIAS_F)));
                float p3 = __fdividef(1.f, 1.f + __expf(-(a4[3] + ATTN_BIAS_F)));
                if (ab) {
                    float2 v0 = {p0, p1}, v1 = {p2, p3};
                    *(float2*)(ab + (size_t)r1 * NSEQ + c) = v0;
                    *(float2*)(ab + (size_t)(r1 + 8) * NSEQ + c) = v1;
                }
                __nv_bfloat16 h0, h1, h2, h3, l0, l1, l2, l3;
                splitf(p0, h0, l0); splitf(p1, h1, l1);
                splitf(p2, h2, l2); splitf(p3, h3, l3);
                *(uint32_t*)(ph + r1 * VPS + c) = b2u(h0, h1);
                *(uint32_t*)(pl + r1 * VPS + c) = b2u(l0, l1);
                *(uint32_t*)(ph + (r1 + 8) * VPS + c) = b2u(h2, h3);
                *(uint32_t*)(pl + (r1 + 8) * VPS + c) = b2u(l2, l3);
            }
        }
        __syncthreads();

        // ---- O += P @ V ----
#pragma unroll
        for (int ks = 0; ks < 8; ks++) {
            const int k0 = ks * 16;
            uint32_t vbh[4][2], vbl[4][2];
#pragma unroll
            for (int nt = 0; nt < 4; nt++) {
                ldb_frag(vbh[nt], vh, wn2 * 32 + nt * 8, k0, VPS, grp, qd);
                ldb_frag(vbl[nt], vl, wn2 * 32 + nt * 8, k0, VPS, grp, qd);
            }
#pragma unroll
            for (int mt = 0; mt < 2; mt++) {
                uint32_t pah[4], pal[4];
                lda_frag(pah, ph, wm2 * 32 + mt * 16, k0, VPS, grp, qd);
                lda_frag(pal, pl, wm2 * 32 + mt * 16, k0, VPS, grp, qd);
#pragma unroll
                for (int nt = 0; nt < 4; nt++) {
                    mma_bf16(oacc[mt][nt], pah, vbh[nt]);
                    mma_bf16(oacc[mt][nt], pah, vbl[nt]);
                    mma_bf16(oacc[mt][nt], pal, vbh[nt]);
                }
            }
        }
        __syncthreads();   // protect k/v/p smem before next tile
    }

    // ---- epilogue: O -> g_av [B,N,H*DH] (+ optional copy to out) ----
#pragma unroll
    for (int mt = 0; mt < 2; mt++) {
        int r = row0 + wm2 * 32 + mt * 16 + grp;
#pragma unroll
        for (int nt = 0; nt < 4; nt++) {
            int d = wn2 * 32 + nt * 8 + qd * 2;
            float* a4 = oacc[mt][nt];
            size_t base = (((size_t)b * NSEQ + r) * HN + h) * DH + d;
            float2 v0 = {a4[0], a4[1]}, v1 = {a4[2], a4[3]};
            *(float2*)(g_av + base) = v0;
            *(float2*)(g_av + base + 8 * (size_t)CDIM) = v1;
            if (av_out2) {
                *(float2*)(av_out2 + base) = v0;
                *(float2*)(av_out2 + base + 8 * (size_t)CDIM) = v1;
            }
        }
    }
}

// ---------------------------------------------------------------------------
// Launch
// ---------------------------------------------------------------------------
extern "C" void kernel_launch(void* const* d_in, const int* in_sizes, int n_in,
                              void* d_out, int out_size)
{
    const float* x     = (const float*)d_in[0];
    const float* wqkv  = (const float*)d_in[1];
    const float* wproj = (const float*)d_in[2];
    float* out = (float*)d_out;

    const size_t SZ_ATTN = (size_t)BSZ * HN * NSEQ * NSEQ;
    const size_t SZ_AV   = (size_t)BSZ * NSEQ * CDIM;
    const bool full = ((size_t)out_size >= SZ_ATTN + 2 * SZ_AV);

    static float* g_av_dev = nullptr;
    static bool attr_done = false;
    if (!attr_done) {
        cudaFuncSetAttribute(attn_kernel,
                             cudaFuncAttributeMaxDynamicSharedMemorySize, ATTN_SMEM_BYTES);
        cudaFuncSetAttribute(tc_gemm<0>,
                             cudaFuncAttributeMaxDynamicSharedMemorySize, TCGEMM_SMEM);
        cudaFuncSetAttribute(tc_gemm<1>,
                             cudaFuncAttributeMaxDynamicSharedMemorySize, TCGEMM_SMEM);
        cudaGetSymbolAddress((void**)&g_av_dev, g_av);
        attr_done = true;
    }

    // 1) QKV projection -> g_qkv scatter (q pre-scaled)
    tc_gemm<1><<<dim3(3 * CDIM / 128, (BSZ * NSEQ) / 128), 256, TCGEMM_SMEM>>>(
        x, wqkv, nullptr, BSZ * NSEQ, 3 * CDIM, CDIM);

    // 2) Fused sigmoid attention
    float* attn_dst = full ? out : nullptr;
    float* av_dst2  = full ? out + SZ_ATTN : nullptr;
    attn_kernel<<<dim3(NSEQ / 128, BSZ * HN), 256, ATTN_SMEM_BYTES>>>(attn_dst, av_dst2);

    // 3) Output projection
    const float* av_src = full ? (const float*)(out + SZ_ATTN)
                               : (const float*)g_av_dev;
    float* proj_dst = full ? out + SZ_ATTN + SZ_AV : out;
    tc_gemm<0><<<dim3(CDIM / 128, (BSZ * NSEQ) / 128), 256, TCGEMM_SMEM>>>(
        av_src, wproj, proj_dst, BSZ * NSEQ, CDIM, CDIM);
}

// round 7
// speedup vs baseline: 2.8479x; 1.3482x over previous
#include <cuda_runtime.h>
#include <cuda_bf16.h>
#include <cstdint>
#include <cstddef>

// Problem constants
#define BSZ   2
#define NSEQ  2048
#define CDIM  1024
#define HN    16
#define DH    64
#define QSCALE 0.125f            // DH^-0.5
#define ATTN_BIAS_F (-7.625f)

#define NELEM_X   ((size_t)BSZ * NSEQ * CDIM)        // 4,194,304
#define NELEM_W   ((size_t)3 * CDIM * CDIM)          // 3,145,728
#define NELEM_HD  ((size_t)BSZ * HN * NSEQ * DH)     // 4,194,304

// Pre-split operands (bf16 hi/lo)
__device__ __nv_bfloat16 g_xhi[NELEM_X], g_xlo[NELEM_X];
__device__ __nv_bfloat16 g_whi[NELEM_W], g_wlo[NELEM_W];
// Q,K: [B][H][N][DH] (q pre-scaled); V transposed: [B][H][DH][N]
__device__ __nv_bfloat16 g_qhi[NELEM_HD], g_qlo[NELEM_HD];
__device__ __nv_bfloat16 g_khi[NELEM_HD], g_klo[NELEM_HD];
__device__ __nv_bfloat16 g_vhi[NELEM_HD], g_vlo[NELEM_HD];
// attn_times_v fp32 scratch
__device__ float g_av[(size_t)BSZ * NSEQ * CDIM];

// ---------------------------------------------------------------------------
// Helpers
// ---------------------------------------------------------------------------
__device__ __forceinline__ uint32_t smem_u32(const void* p) {
    uint32_t a;
    asm("{ .reg .u64 t; cvta.to.shared.u64 t, %1; cvt.u32.u64 %0, t; }"
        : "=r"(a) : "l"(p));
    return a;
}

__device__ __forceinline__ void mma_bf16(float c[4], const uint32_t a[4],
                                         const uint32_t b[2]) {
    asm volatile(
        "mma.sync.aligned.m16n8k16.row.col.f32.bf16.bf16.f32 "
        "{%0,%1,%2,%3}, {%4,%5,%6,%7}, {%8,%9}, {%0,%1,%2,%3};\n"
        : "+f"(c[0]), "+f"(c[1]), "+f"(c[2]), "+f"(c[3])
        : "r"(a[0]), "r"(a[1]), "r"(a[2]), "r"(a[3]), "r"(b[0]), "r"(b[1]));
}

__device__ __forceinline__ void lda_frag(uint32_t a[4], const __nv_bfloat16* base,
                                         int row0, int k0, int S, int grp, int qd) {
    const __nv_bfloat16* p = base + (size_t)(row0 + grp) * S + k0 + qd * 2;
    a[0] = *(const uint32_t*)p;
    a[1] = *(const uint32_t*)(p + 8 * S);
    a[2] = *(const uint32_t*)(p + 8);
    a[3] = *(const uint32_t*)(p + 8 * S + 8);
}
__device__ __forceinline__ void ldb_frag(uint32_t b[2], const __nv_bfloat16* base,
                                         int n0, int k0, int S, int grp, int qd) {
    const __nv_bfloat16* p = base + (size_t)(n0 + grp) * S + k0 + qd * 2;
    b[0] = *(const uint32_t*)p;
    b[1] = *(const uint32_t*)(p + 8);
}

__device__ __forceinline__ void splitf(float v, __nv_bfloat16& h, __nv_bfloat16& l) {
    h = __float2bfloat16_rn(v);
    l = __float2bfloat16_rn(v - __bfloat162float(h));
}
__device__ __forceinline__ uint32_t b2u(__nv_bfloat16 a, __nv_bfloat16 b) {
    __nv_bfloat162 t(a, b);
    return *reinterpret_cast<uint32_t*>(&t);
}
__device__ __forceinline__ void split4(float4 v, uint2& hi, uint2& lo) {
    __nv_bfloat16 h0, h1, h2, h3, l0, l1, l2, l3;
    splitf(v.x, h0, l0); splitf(v.y, h1, l1);
    splitf(v.z, h2, l2); splitf(v.w, h3, l3);
    hi.x = b2u(h0, h1); hi.y = b2u(h2, h3);
    lo.x = b2u(l0, l1); lo.y = b2u(l2, l3);
}

// cp.async (LDGSTS)
__device__ __forceinline__ void cp16(uint32_t dst, const void* src) {
    asm volatile("cp.async.cg.shared.global [%0], [%1], 16;" :: "r"(dst), "l"(src));
}
#define CP_COMMIT() asm volatile("cp.async.commit_group;" ::: "memory")
#define CP_WAIT(N)  asm volatile("cp.async.wait_group %0;" :: "n"(N) : "memory")

// ---------------------------------------------------------------------------
// Elementwise split converters
// ---------------------------------------------------------------------------
__global__ void convert_x(const float* __restrict__ src) {
    int i = blockIdx.x * blockDim.x + threadIdx.x;   // over float4s
    float4 v = ((const float4*)src)[i];
    uint2 hi, lo; split4(v, hi, lo);
    ((uint2*)g_xhi)[i] = hi;
    ((uint2*)g_xlo)[i] = lo;
}
__global__ void convert_w(const float* __restrict__ src) {
    int i = blockIdx.x * blockDim.x + threadIdx.x;
    float4 v = ((const float4*)src)[i];
    uint2 hi, lo; split4(v, hi, lo);
    ((uint2*)g_whi)[i] = hi;
    ((uint2*)g_wlo)[i] = lo;
}

// ---------------------------------------------------------------------------
// QKV GEMM: [4096,1024] @ [3072,1024]^T, bf16 hi/lo inputs, cp.async
// double-buffered, 3-pass split MMA. Epilogue: split outputs to
// g_q/g_k (row-major, q scaled) and g_v (transposed [d][n]).
// smem: 2 stages x (Ah,Al,Bh,Bl)[128][72] bf16 = 147456 B
// ---------------------------------------------------------------------------
#define GS 72
#define QKV_STAGE  36864                      // elements per stage (4 * 9216)
#define QKV_SMEM   (2 * QKV_STAGE * 2)        // bytes

__global__ void __launch_bounds__(256, 1)
tc_gemm_qkv()
{
    extern __shared__ __nv_bfloat16 smg[];
    const uint32_t sbase = smem_u32(smg);
    const int tid = threadIdx.x;
    const int wid = tid >> 5, lane = tid & 31;
    const int grp = lane >> 2, qd = lane & 3;
    const int wm = wid >> 2, wn = wid & 3;
    const int row0 = blockIdx.y * 128, col0 = blockIdx.x * 128;

    auto stage_load = [&](int s, int kb) {
#pragma unroll
        for (int it = 0; it < 4; it++) {
            int f = tid + 256 * it;
            int row = f >> 3, q = f & 7;
            size_t asrc = (size_t)(row0 + row) * CDIM + kb * 64 + q * 8;
            size_t bsrc = (size_t)(col0 + row) * CDIM + kb * 64 + q * 8;
            uint32_t off = sbase + (uint32_t)(s * QKV_STAGE + row * GS + q * 8) * 2;
            cp16(off,             g_xhi + asrc);
            cp16(off +  9216 * 2, g_xlo + asrc);
            cp16(off + 18432 * 2, g_whi + bsrc);
            cp16(off + 27648 * 2, g_wlo + bsrc);
        }
    };

    float acc[4][4][4];
#pragma unroll
    for (int i = 0; i < 4; i++)
#pragma unroll
        for (int j = 0; j < 4; j++)
#pragma unroll
            for (int t = 0; t < 4; t++) acc[i][j][t] = 0.f;

    stage_load(0, 0); CP_COMMIT();

    for (int kb = 0; kb < 16; kb++) {
        if (kb < 15) { stage_load((kb + 1) & 1, kb + 1); CP_COMMIT(); CP_WAIT(1); }
        else         { CP_WAIT(0); }
        __syncthreads();

        const __nv_bfloat16* Ah = smg + (kb & 1) * QKV_STAGE;
        const __nv_bfloat16* Al = Ah + 9216;
        const __nv_bfloat16* Bh = Ah + 18432;
        const __nv_bfloat16* Bl = Ah + 27648;

#pragma unroll
        for (int ks = 0; ks < 4; ks++) {
            const int k0 = ks * 16;
            uint32_t bh[4][2], bl[4][2];
#pragma unroll
            for (int nt = 0; nt < 4; nt++) {
                ldb_frag(bh[nt], Bh, wn * 32 + nt * 8, k0, GS, grp, qd);
                ldb_frag(bl[nt], Bl, wn * 32 + nt * 8, k0, GS, grp, qd);
            }
#pragma unroll
            for (int mt = 0; mt < 4; mt++) {
                uint32_t ah[4], al[4];
                lda_frag(ah, Ah, wm * 64 + mt * 16, k0, GS, grp, qd);
                lda_frag(al, Al, wm * 64 + mt * 16, k0, GS, grp, qd);
#pragma unroll
                for (int nt = 0; nt < 4; nt++) {
                    mma_bf16(acc[mt][nt], ah, bh[nt]);
                    mma_bf16(acc[mt][nt], ah, bl[nt]);
                    mma_bf16(acc[mt][nt], al, bh[nt]);
                }
            }
        }
        __syncthreads();
    }

    // epilogue: scatter split outputs
#pragma unroll
    for (int mt = 0; mt < 4; mt++) {
        int r = row0 + wm * 64 + mt * 16 + grp;
        int b0 = r >> 11, n0 = r & 2047;
#pragma unroll
        for (int nt = 0; nt < 4; nt++) {
            int c3 = col0 + wn * 32 + nt * 8 + qd * 2;
            int which = c3 >> 10;
            int cc = c3 & 1023;
            int hh = cc >> 6;
            int d = cc & 63;
            float mul = (which == 0) ? QSCALE : 1.0f;
            float* a4 = acc[mt][nt];
            float v0 = a4[0] * mul, v1 = a4[1] * mul;   // row n0,   cols d, d+1
            float v2 = a4[2] * mul, v3 = a4[3] * mul;   // row n0+8
            __nv_bfloat16 h0, h1, h2, h3, l0, l1, l2, l3;
            splitf(v0, h0, l0); splitf(v1, h1, l1);
            splitf(v2, h2, l2); splitf(v3, h3, l3);
            size_t head = ((size_t)b0 * HN + hh) * (size_t)NSEQ * DH;
            if (which < 2) {
                __nv_bfloat16* dhi = which ? g_khi : g_qhi;
                __nv_bfloat16* dlo = which ? g_klo : g_qlo;
                size_t idx = head + (size_t)n0 * DH + d;
                *(uint32_t*)(dhi + idx) = b2u(h0, h1);
                *(uint32_t*)(dlo + idx) = b2u(l0, l1);
                *(uint32_t*)(dhi + idx + 8 * DH) = b2u(h2, h3);
                *(uint32_t*)(dlo + idx + 8 * DH) = b2u(l2, l3);
            } else {
                // V transposed: [d][n]
                size_t idx = head + (size_t)d * NSEQ + n0;
                g_vhi[idx] = h0;            g_vlo[idx] = l0;
                g_vhi[idx + NSEQ] = h1;     g_vlo[idx + NSEQ] = l1;      // d+1
                g_vhi[idx + 8] = h2;        g_vlo[idx + 8] = l2;         // n0+8
                g_vhi[idx + NSEQ + 8] = h3; g_vlo[idx + NSEQ + 8] = l3;
            }
        }
    }
}

// ---------------------------------------------------------------------------
// Fused sigmoid attention, FA2 layout.
// CTA = 128 q-rows of one (b,h), 8 warps; warp w owns q-rows [16w,16w+16)
// x all 128 keys. P stays in registers (S c-frags -> PV a-frags).
// K/V^T tiles double-buffered via cp.async.
// smem elements: Qh[128][72], Ql; K 2x(hi+lo)[128][72]; V^T 2x(hi+lo)[64][136]
// ---------------------------------------------------------------------------
#define VPS 136
#define SQ_H 0
#define SQ_L 9216
#define SK_BASE 18432            // + s*18432 ; lo at +9216
#define SV_BASE 55296            // + s*17408 ; lo at +8704
#define ATTN_SMEM ((55296 + 2 * 17408) * 2)   // 180224 bytes

__global__ void __launch_bounds__(256, 1)
attn_kernel2(float* __restrict__ attn_out, float* __restrict__ av_out2)
{
    extern __shared__ __nv_bfloat16 sma[];
    const uint32_t sbase = smem_u32(sma);
    const int tid = threadIdx.x;
    const int wid = tid >> 5, lane = tid & 31;
    const int grp = lane >> 2, qd = lane & 3;
    const int row0 = blockIdx.x * 128;
    const int bhid = blockIdx.y;
    const int b = bhid >> 4, h = bhid & 15;
    const size_t head = ((size_t)b * HN + h) * (size_t)NSEQ * DH;

    auto load_kv = [&](int jt_, int s) {
#pragma unroll
        for (int it = 0; it < 4; it++) {
            int f = tid + 256 * it;
            {   // K tile: [128 keys][64 d]
                int row = f >> 3, q = f & 7;
                size_t src = head + (size_t)(jt_ * 128 + row) * DH + q * 8;
                uint32_t off = sbase + (uint32_t)(SK_BASE + s * 18432 + row * GS + q * 8) * 2;
                cp16(off,            g_khi + src);
                cp16(off + 9216 * 2, g_klo + src);
            }
            {   // V^T tile: [64 d][128 keys]
                int row = f >> 4, q = f & 15;
                size_t src = head + (size_t)row * NSEQ + (size_t)jt_ * 128 + q * 8;
                uint32_t off = sbase + (uint32_t)(SV_BASE + s * 17408 + row * VPS + q * 8) * 2;
                cp16(off,            g_vhi + src);
                cp16(off + 8704 * 2, g_vlo + src);
            }
        }
    };

    // prologue: Q + tile 0
#pragma unroll
    for (int it = 0; it < 4; it++) {
        int f = tid + 256 * it;
        int row = f >> 3, q = f & 7;
        size_t src = head + (size_t)(row0 + row) * DH + q * 8;
        uint32_t off = sbase + (uint32_t)(row * GS + q * 8) * 2;
        cp16(off,            g_qhi + src);
        cp16(off + 9216 * 2, g_qlo + src);
    }
    load_kv(0, 0);
    CP_COMMIT();
    CP_WAIT(0);
    __syncthreads();

    float oacc[8][4];
#pragma unroll
    for (int i = 0; i < 8; i++)
#pragma unroll
        for (int t = 0; t < 4; t++) oacc[i][t] = 0.f;

    for (int jt = 0; jt < NSEQ / 128; jt++) {
        if (jt < 15) { load_kv(jt + 1, (jt + 1) & 1); CP_COMMIT(); CP_WAIT(1); }
        else         { CP_WAIT(0); }
        __syncthreads();

        const __nv_bfloat16* kh = sma + SK_BASE + (jt & 1) * 18432;
        const __nv_bfloat16* kl = kh + 9216;
        const __nv_bfloat16* vh = sma + SV_BASE + (jt & 1) * 17408;
        const __nv_bfloat16* vl = vh + 8704;

        // ---- S = Q K^T : sacc[nt] covers keys [8nt, 8nt+8) ----
        float sacc[16][4];
#pragma unroll
        for (int i = 0; i < 16; i++)
#pragma unroll
            for (int t = 0; t < 4; t++) sacc[i][t] = 0.f;

#pragma unroll
        for (int ks = 0; ks < 4; ks++) {
            const int k0 = ks * 16;
            uint32_t qfh[4], qfl[4];
            lda_frag(qfh, sma + SQ_H, wid * 16, k0, GS, grp, qd);
            lda_frag(qfl, sma + SQ_L, wid * 16, k0, GS, grp, qd);
#pragma unroll
            for (int nt = 0; nt < 16; nt++) {
                uint32_t bh[2], bl[2];
                ldb_frag(bh, kh, nt * 8, k0, GS, grp, qd);
                ldb_frag(bl, kl, nt * 8, k0, GS, grp, qd);
                mma_bf16(sacc[nt], qfh, bh);
                mma_bf16(sacc[nt], qfh, bl);
                mma_bf16(sacc[nt], qfl, bh);
            }
        }

        // ---- sigmoid + attn store + register P -> PV ----
        float* ab = attn_out
            ? attn_out + ((size_t)bhid * NSEQ + row0 + wid * 16 + grp) * NSEQ
                       + (size_t)jt * 128
            : nullptr;

#pragma unroll
        for (int kc = 0; kc < 8; kc++) {
            float* c0 = sacc[2 * kc];
            float* c1 = sacc[2 * kc + 1];
            float p0 = __fdividef(1.f, 1.f + __expf(-(c0[0] + ATTN_BIAS_F)));
            float p1 = __fdividef(1.f, 1.f + __expf(-(c0[1] + ATTN_BIAS_F)));
            float p2 = __fdividef(1.f, 1.f + __expf(-(c0[2] + ATTN_BIAS_F)));
            float p3 = __fdividef(1.f, 1.f + __expf(-(c0[3] + ATTN_BIAS_F)));
            float p4 = __fdividef(1.f, 1.f + __expf(-(c1[0] + ATTN_BIAS_F)));
            float p5 = __fdividef(1.f, 1.f + __expf(-(c1[1] + ATTN_BIAS_F)));
            float p6 = __fdividef(1.f, 1.f + __expf(-(c1[2] + ATTN_BIAS_F)));
            float p7 = __fdividef(1.f, 1.f + __expf(-(c1[3] + ATTN_BIAS_F)));
            if (ab) {
                float2 w0 = {p0, p1}, w1 = {p2, p3}, w2 = {p4, p5}, w3 = {p6, p7};
                *(float2*)(ab + kc * 16 + 2 * qd) = w0;
                *(float2*)(ab + 8 * NSEQ + kc * 16 + 2 * qd) = w1;
                *(float2*)(ab + kc * 16 + 8 + 2 * qd) = w2;
                *(float2*)(ab + 8 * NSEQ + kc * 16 + 8 + 2 * qd) = w3;
            }
            // A-frags: a0=(grp,k 2qd)=p0p1; a1=(grp+8)=p2p3; a2=(grp,k8+2qd)=p4p5; a3=p6p7
            __nv_bfloat16 h0, h1, h2, h3, h4, h5, h6, h7;
            __nv_bfloat16 l0, l1, l2, l3, l4, l5, l6, l7;
            splitf(p0, h0, l0); splitf(p1, h1, l1); splitf(p2, h2, l2); splitf(p3, h3, l3);
            splitf(p4, h4, l4); splitf(p5, h5, l5); splitf(p6, h6, l6); splitf(p7, h7, l7);
            uint32_t pah[4] = { b2u(h0, h1), b2u(h2, h3), b2u(h4, h5), b2u(h6, h7) };
            uint32_t pal[4] = { b2u(l0, l1), b2u(l2, l3), b2u(l4, l5), b2u(l6, l7) };
#pragma unroll
            for (int dt = 0; dt < 8; dt++) {
                uint32_t vb[2], vbl[2];
                ldb_frag(vb,  vh, dt * 8, kc * 16, VPS, grp, qd);
                ldb_frag(vbl, vl, dt * 8, kc * 16, VPS, grp, qd);
                mma_bf16(oacc[dt], pah, vb);
                mma_bf16(oacc[dt], pah, vbl);
                mma_bf16(oacc[dt], pal, vb);
            }
        }
        __syncthreads();
    }

    // ---- epilogue: O -> g_av (+ optional out copy), [B,N,H,DH] ----
    const int r = row0 + wid * 16 + grp;
#pragma unroll
    for (int dt = 0; dt < 8; dt++) {
        int d = dt * 8 + qd * 2;
        size_t base = (((size_t)b * NSEQ + r) * HN + h) * DH + d;
        float2 v0 = {oacc[dt][0], oacc[dt][1]};
        float2 v1 = {oacc[dt][2], oacc[dt][3]};
        *(float2*)(g_av + base) = v0;
        *(float2*)(g_av + base + 8 * (size_t)CDIM) = v1;
        if (av_out2) {
            *(float2*)(av_out2 + base) = v0;
            *(float2*)(av_out2 + base + 8 * (size_t)CDIM) = v1;
        }
    }
}

// ---------------------------------------------------------------------------
// Output projection GEMM (fp32 in, in-kernel split, single-buffered)
// ---------------------------------------------------------------------------
#define PROJ_SMEM (4 * 128 * GS * 2)

__global__ void __launch_bounds__(256, 1)
tc_gemm_proj(const float* __restrict__ A, const float* __restrict__ Bw,
             float* __restrict__ Cout, int M, int Nn, int K)
{
    extern __shared__ __nv_bfloat16 smg[];
    __nv_bfloat16* Ah = smg;
    __nv_bfloat16* Al = Ah + 128 * GS;
    __nv_bfloat16* Bh = Al + 128 * GS;
    __nv_bfloat16* Bl = Bh + 128 * GS;

    const int tid = threadIdx.x;
    const int wid = tid >> 5, lane = tid & 31;
    const int grp = lane >> 2, qd = lane & 3;
    const int wm = wid >> 2, wn = wid & 3;
    const int row0 = blockIdx.y * 128, col0 = blockIdx.x * 128;

    float acc[4][4][4];
#pragma unroll
    for (int i = 0; i < 4; i++)
#pragma unroll
        for (int j = 0; j < 4; j++)
#pragma unroll
            for (int t = 0; t < 4; t++) acc[i][j][t] = 0.f;

    const int nchunks = K >> 6;
    for (int kb = 0; kb < nchunks; kb++) {
#pragma unroll
        for (int s = 0; s < 8; s++) {
            int f = tid + 256 * s;
            int row = f >> 4, q = f & 15;
            float4 va = *(const float4*)(A + (size_t)(row0 + row) * K + kb * 64 + q * 4);
            uint2 hi, lo; split4(va, hi, lo);
            *(uint2*)(Ah + row * GS + q * 4) = hi;
            *(uint2*)(Al + row * GS + q * 4) = lo;
            float4 vb = *(const float4*)(Bw + (size_t)(col0 + row) * K + kb * 64 + q * 4);
            split4(vb, hi, lo);
            *(uint2*)(Bh + row * GS + q * 4) = hi;
            *(uint2*)(Bl + row * GS + q * 4) = lo;
        }
        __syncthreads();

#pragma unroll
        for (int ks = 0; ks < 4; ks++) {
            const int k0 = ks * 16;
            uint32_t bh[4][2], bl[4][2];
#pragma unroll
            for (int nt = 0; nt < 4; nt++) {
                ldb_frag(bh[nt], Bh, wn * 32 + nt * 8, k0, GS, grp, qd);
                ldb_frag(bl[nt], Bl, wn * 32 + nt * 8, k0, GS, grp, qd);
            }
#pragma unroll
            for (int mt = 0; mt < 4; mt++) {
                uint32_t ah[4], al[4];
                lda_frag(ah, Ah, wm * 64 + mt * 16, k0, GS, grp, qd);
                lda_frag(al, Al, wm * 64 + mt * 16, k0, GS, grp, qd);
#pragma unroll
                for (int nt = 0; nt < 4; nt++) {
                    mma_bf16(acc[mt][nt], ah, bh[nt]);
                    mma_bf16(acc[mt][nt], ah, bl[nt]);
                    mma_bf16(acc[mt][nt], al, bh[nt]);
                }
            }
        }
        __syncthreads();
    }

#pragma unroll
    for (int mt = 0; mt < 4; mt++) {
        int r = row0 + wm * 64 + mt * 16 + grp;
#pragma unroll
        for (int nt = 0; nt < 4; nt++) {
            int cl = wn * 32 + nt * 8 + qd * 2;
            float* a4 = acc[mt][nt];
            float2 v0 = {a4[0], a4[1]};
            float2 v1 = {a4[2], a4[3]};
            *(float2*)(Cout + (size_t)r * Nn + col0 + cl) = v0;
            *(float2*)(Cout + (size_t)(r + 8) * Nn + col0 + cl) = v1;
        }
    }
}

// ---------------------------------------------------------------------------
// Launch
// ---------------------------------------------------------------------------
extern "C" void kernel_launch(void* const* d_in, const int* in_sizes, int n_in,
                              void* d_out, int out_size)
{
    const float* x     = (const float*)d_in[0];
    const float* wqkv  = (const float*)d_in[1];
    const float* wproj = (const float*)d_in[2];
    float* out = (float*)d_out;

    const size_t SZ_ATTN = (size_t)BSZ * HN * NSEQ * NSEQ;
    const size_t SZ_AV   = (size_t)BSZ * NSEQ * CDIM;
    const bool full = ((size_t)out_size >= SZ_ATTN + 2 * SZ_AV);

    static float* g_av_dev = nullptr;
    static bool attr_done = false;
    if (!attr_done) {
        cudaFuncSetAttribute(tc_gemm_qkv,
                             cudaFuncAttributeMaxDynamicSharedMemorySize, QKV_SMEM);
        cudaFuncSetAttribute(attn_kernel2,
                             cudaFuncAttributeMaxDynamicSharedMemorySize, ATTN_SMEM);
        cudaFuncSetAttribute(tc_gemm_proj,
                             cudaFuncAttributeMaxDynamicSharedMemorySize, PROJ_SMEM);
        cudaGetSymbolAddress((void**)&g_av_dev, g_av);
        attr_done = true;
    }

    // 0) split-convert x and wqkv to bf16 hi/lo
    convert_x<<<(int)(NELEM_X / 4 / 256), 256>>>(x);
    convert_w<<<(int)(NELEM_W / 4 / 256), 256>>>(wqkv);

    // 1) QKV projection -> split q/k (row-major) + v (transposed)
    tc_gemm_qkv<<<dim3(3 * CDIM / 128, (BSZ * NSEQ) / 128), 256, QKV_SMEM>>>();

    // 2) Fused sigmoid attention
    float* attn_dst = full ? out : nullptr;
    float* av_dst2  = full ? out + SZ_ATTN : nullptr;
    attn_kernel2<<<dim3(NSEQ / 128, BSZ * HN), 256, ATTN_SMEM>>>(attn_dst, av_dst2);

    // 3) Output projection
    const float* av_src = full ? (const float*)(out + SZ_ATTN)
                               : (const float*)g_av_dev;
    float* proj_dst = full ? out + SZ_ATTN + SZ_AV : out;
    tc_gemm_proj<<<dim3(CDIM / 128, (BSZ * NSEQ) / 128), 256, PROJ_SMEM>>>(
        av_src, wproj, proj_dst, BSZ * NSEQ, CDIM, CDIM);
}

// round 8
// speedup vs baseline: 2.9057x; 1.0203x over previous
#include <cuda_runtime.h>
#include <cuda_bf16.h>
#include <cstdint>
#include <cstddef>

// Problem constants
#define BSZ   2
#define NSEQ  2048
#define CDIM  1024
#define HN    16
#define DH    64
#define QSCALE 0.125f            // DH^-0.5
#define ATTN_BIAS_F (-7.625f)

#define NELEM_X   ((size_t)BSZ * NSEQ * CDIM)        // 4,194,304
#define NELEM_W   ((size_t)3 * CDIM * CDIM)          // 3,145,728
#define NELEM_WP  ((size_t)CDIM * CDIM)              // 1,048,576
#define NELEM_HD  ((size_t)BSZ * HN * NSEQ * DH)     // 4,194,304

// Pre-split operands (bf16 hi/lo)
__device__ __nv_bfloat16 g_xhi[NELEM_X],  g_xlo[NELEM_X];
__device__ __nv_bfloat16 g_whi[NELEM_W],  g_wlo[NELEM_W];
__device__ __nv_bfloat16 g_wphi[NELEM_WP], g_wplo[NELEM_WP];
// Q,K: [B][H][N][DH] (q pre-scaled); V transposed: [B][H][DH][N]
__device__ __nv_bfloat16 g_qhi[NELEM_HD], g_qlo[NELEM_HD];
__device__ __nv_bfloat16 g_khi[NELEM_HD], g_klo[NELEM_HD];
__device__ __nv_bfloat16 g_vhi[NELEM_HD], g_vlo[NELEM_HD];
// attn_times_v: split bf16 (for proj GEMM) + fp32 fallback scratch
__device__ __nv_bfloat16 g_avhi[NELEM_X], g_avlo[NELEM_X];
__device__ float g_av[NELEM_X];

// ---------------------------------------------------------------------------
// Helpers
// ---------------------------------------------------------------------------
__device__ __forceinline__ uint32_t smem_u32(const void* p) {
    uint32_t a;
    asm("{ .reg .u64 t; cvta.to.shared.u64 t, %1; cvt.u32.u64 %0, t; }"
        : "=r"(a) : "l"(p));
    return a;
}

__device__ __forceinline__ void mma_bf16(float c[4], const uint32_t a[4],
                                         const uint32_t b[2]) {
    asm volatile(
        "mma.sync.aligned.m16n8k16.row.col.f32.bf16.bf16.f32 "
        "{%0,%1,%2,%3}, {%4,%5,%6,%7}, {%8,%9}, {%0,%1,%2,%3};\n"
        : "+f"(c[0]), "+f"(c[1]), "+f"(c[2]), "+f"(c[3])
        : "r"(a[0]), "r"(a[1]), "r"(a[2]), "r"(a[3]), "r"(b[0]), "r"(b[1]));
}

__device__ __forceinline__ void lda_frag(uint32_t a[4], const __nv_bfloat16* base,
                                         int row0, int k0, int S, int grp, int qd) {
    const __nv_bfloat16* p = base + (size_t)(row0 + grp) * S + k0 + qd * 2;
    a[0] = *(const uint32_t*)p;
    a[1] = *(const uint32_t*)(p + 8 * S);
    a[2] = *(const uint32_t*)(p + 8);
    a[3] = *(const uint32_t*)(p + 8 * S + 8);
}
__device__ __forceinline__ void ldb_frag(uint32_t b[2], const __nv_bfloat16* base,
                                         int n0, int k0, int S, int grp, int qd) {
    const __nv_bfloat16* p = base + (size_t)(n0 + grp) * S + k0 + qd * 2;
    b[0] = *(const uint32_t*)p;
    b[1] = *(const uint32_t*)(p + 8);
}

__device__ __forceinline__ void splitf(float v, __nv_bfloat16& h, __nv_bfloat16& l) {
    h = __float2bfloat16_rn(v);
    l = __float2bfloat16_rn(v - __bfloat162float(h));
}
__device__ __forceinline__ uint32_t b2u(__nv_bfloat16 a, __nv_bfloat16 b) {
    __nv_bfloat162 t(a, b);
    return *reinterpret_cast<uint32_t*>(&t);
}
__device__ __forceinline__ void split4(float4 v, uint2& hi, uint2& lo) {
    __nv_bfloat16 h0, h1, h2, h3, l0, l1, l2, l3;
    splitf(v.x, h0, l0); splitf(v.y, h1, l1);
    splitf(v.z, h2, l2); splitf(v.w, h3, l3);
    hi.x = b2u(h0, h1); hi.y = b2u(h2, h3);
    lo.x = b2u(l0, l1); lo.y = b2u(l2, l3);
}

__device__ __forceinline__ void cp16(uint32_t dst, const void* src) {
    asm volatile("cp.async.cg.shared.global [%0], [%1], 16;" :: "r"(dst), "l"(src));
}
#define CP_COMMIT() asm volatile("cp.async.commit_group;" ::: "memory")
#define CP_WAIT(N)  asm volatile("cp.async.wait_group %0;" :: "n"(N) : "memory")

// ---------------------------------------------------------------------------
// Elementwise split converters
// ---------------------------------------------------------------------------
__global__ void convert_x(const float* __restrict__ src) {
    int i = blockIdx.x * blockDim.x + threadIdx.x;
    float4 v = ((const float4*)src)[i];
    uint2 hi, lo; split4(v, hi, lo);
    ((uint2*)g_xhi)[i] = hi;
    ((uint2*)g_xlo)[i] = lo;
}
__global__ void convert_w(const float* __restrict__ src) {
    int i = blockIdx.x * blockDim.x + threadIdx.x;
    float4 v = ((const float4*)src)[i];
    uint2 hi, lo; split4(v, hi, lo);
    ((uint2*)g_whi)[i] = hi;
    ((uint2*)g_wlo)[i] = lo;
}
__global__ void convert_wp(const float* __restrict__ src) {
    int i = blockIdx.x * blockDim.x + threadIdx.x;
    float4 v = ((const float4*)src)[i];
    uint2 hi, lo; split4(v, hi, lo);
    ((uint2*)g_wphi)[i] = hi;
    ((uint2*)g_wplo)[i] = lo;
}

// ---------------------------------------------------------------------------
// Shared GEMM mainloop body (bf16 hi/lo operands already staged in smem).
// ILP-friendly MMA order: 3 split-passes sweep 4 independent accumulators.
// ---------------------------------------------------------------------------
#define GS 72
#define QKV_STAGE  36864                      // elements per stage (4 * 9216)
#define QKV_SMEM   (2 * QKV_STAGE * 2)        // 147456 bytes

__device__ __forceinline__ void gemm_mainloop_step(
    const __nv_bfloat16* Ah, float acc[4][4][4],
    int wm, int wn, int grp, int qd)
{
    const __nv_bfloat16* Al = Ah + 9216;
    const __nv_bfloat16* Bh = Ah + 18432;
    const __nv_bfloat16* Bl = Ah + 27648;
#pragma unroll
    for (int ks = 0; ks < 4; ks++) {
        const int k0 = ks * 16;
        uint32_t bh[4][2], bl[4][2];
#pragma unroll
        for (int nt = 0; nt < 4; nt++) {
            ldb_frag(bh[nt], Bh, wn * 32 + nt * 8, k0, GS, grp, qd);
            ldb_frag(bl[nt], Bl, wn * 32 + nt * 8, k0, GS, grp, qd);
        }
#pragma unroll
        for (int mt = 0; mt < 4; mt++) {
            uint32_t ah[4], al[4];
            lda_frag(ah, Ah, wm * 64 + mt * 16, k0, GS, grp, qd);
            lda_frag(al, Al, wm * 64 + mt * 16, k0, GS, grp, qd);
            // 3 passes, each sweeping 4 independent accumulators
#pragma unroll
            for (int nt = 0; nt < 4; nt++) mma_bf16(acc[mt][nt], ah, bh[nt]);
#pragma unroll
            for (int nt = 0; nt < 4; nt++) mma_bf16(acc[mt][nt], ah, bl[nt]);
#pragma unroll
            for (int nt = 0; nt < 4; nt++) mma_bf16(acc[mt][nt], al, bh[nt]);
        }
    }
}

// ---------------------------------------------------------------------------
// QKV GEMM: x[4096,1024] @ wqkv[3072,1024]^T, cp.async double-buffered.
// Epilogue: split outputs -> g_q/g_k (row-major, q scaled), g_v ([d][n]).
// ---------------------------------------------------------------------------
__global__ void __launch_bounds__(256, 1)
tc_gemm_qkv()
{
    extern __shared__ __nv_bfloat16 smg[];
    const uint32_t sbase = smem_u32(smg);
    const int tid = threadIdx.x;
    const int wid = tid >> 5, lane = tid & 31;
    const int grp = lane >> 2, qd = lane & 3;
    const int wm = wid >> 2, wn = wid & 3;
    const int row0 = blockIdx.y * 128, col0 = blockIdx.x * 128;

    auto stage_load = [&](int s, int kb) {
#pragma unroll
        for (int it = 0; it < 4; it++) {
            int f = tid + 256 * it;
            int row = f >> 3, q = f & 7;
            size_t asrc = (size_t)(row0 + row) * CDIM + kb * 64 + q * 8;
            size_t bsrc = (size_t)(col0 + row) * CDIM + kb * 64 + q * 8;
            uint32_t off = sbase + (uint32_t)(s * QKV_STAGE + row * GS + q * 8) * 2;
            cp16(off,             g_xhi + asrc);
            cp16(off +  9216 * 2, g_xlo + asrc);
            cp16(off + 18432 * 2, g_whi + bsrc);
            cp16(off + 27648 * 2, g_wlo + bsrc);
        }
    };

    float acc[4][4][4];
#pragma unroll
    for (int i = 0; i < 4; i++)
#pragma unroll
        for (int j = 0; j < 4; j++)
#pragma unroll
            for (int t = 0; t < 4; t++) acc[i][j][t] = 0.f;

    stage_load(0, 0); CP_COMMIT();

    for (int kb = 0; kb < 16; kb++) {
        if (kb < 15) { stage_load((kb + 1) & 1, kb + 1); CP_COMMIT(); CP_WAIT(1); }
        else         { CP_WAIT(0); }
        __syncthreads();
        gemm_mainloop_step(smg + (kb & 1) * QKV_STAGE, acc, wm, wn, grp, qd);
        __syncthreads();
    }

    // epilogue: scatter split outputs
#pragma unroll
    for (int mt = 0; mt < 4; mt++) {
        int r = row0 + wm * 64 + mt * 16 + grp;
        int b0 = r >> 11, n0 = r & 2047;
#pragma unroll
        for (int nt = 0; nt < 4; nt++) {
            int c3 = col0 + wn * 32 + nt * 8 + qd * 2;
            int which = c3 >> 10;
            int cc = c3 & 1023;
            int hh = cc >> 6;
            int d = cc & 63;
            float mul = (which == 0) ? QSCALE : 1.0f;
            float* a4 = acc[mt][nt];
            float v0 = a4[0] * mul, v1 = a4[1] * mul;
            float v2 = a4[2] * mul, v3 = a4[3] * mul;
            __nv_bfloat16 h0, h1, h2, h3, l0, l1, l2, l3;
            splitf(v0, h0, l0); splitf(v1, h1, l1);
            splitf(v2, h2, l2); splitf(v3, h3, l3);
            size_t head = ((size_t)b0 * HN + hh) * (size_t)NSEQ * DH;
            if (which < 2) {
                __nv_bfloat16* dhi = which ? g_khi : g_qhi;
                __nv_bfloat16* dlo = which ? g_klo : g_qlo;
                size_t idx = head + (size_t)n0 * DH + d;
                *(uint32_t*)(dhi + idx) = b2u(h0, h1);
                *(uint32_t*)(dlo + idx) = b2u(l0, l1);
                *(uint32_t*)(dhi + idx + 8 * DH) = b2u(h2, h3);
                *(uint32_t*)(dlo + idx + 8 * DH) = b2u(l2, l3);
            } else {
                size_t idx = head + (size_t)d * NSEQ + n0;
                g_vhi[idx] = h0;            g_vlo[idx] = l0;
                g_vhi[idx + NSEQ] = h1;     g_vlo[idx + NSEQ] = l1;
                g_vhi[idx + 8] = h2;        g_vlo[idx + 8] = l2;
                g_vhi[idx + NSEQ + 8] = h3; g_vlo[idx + NSEQ + 8] = l3;
            }
        }
    }
}

// ---------------------------------------------------------------------------
// Fused sigmoid attention, FA2 layout, ILP-ordered MMAs.
// ---------------------------------------------------------------------------
#define VPS 136
#define SQ_H 0
#define SQ_L 9216
#define SK_BASE 18432            // + s*18432 ; lo at +9216
#define SV_BASE 55296            // + s*17408 ; lo at +8704
#define ATTN_SMEM ((55296 + 2 * 17408) * 2)   // 180224 bytes

__global__ void __launch_bounds__(256, 1)
attn_kernel2(float* __restrict__ attn_out, float* __restrict__ av_out)
{
    extern __shared__ __nv_bfloat16 sma[];
    const uint32_t sbase = smem_u32(sma);
    const int tid = threadIdx.x;
    const int wid = tid >> 5, lane = tid & 31;
    const int grp = lane >> 2, qd = lane & 3;
    const int row0 = blockIdx.x * 128;
    const int bhid = blockIdx.y;
    const int b = bhid >> 4, h = bhid & 15;
    const size_t head = ((size_t)b * HN + h) * (size_t)NSEQ * DH;

    auto load_kv = [&](int jt_, int s) {
#pragma unroll
        for (int it = 0; it < 4; it++) {
            int f = tid + 256 * it;
            {
                int row = f >> 3, q = f & 7;
                size_t src = head + (size_t)(jt_ * 128 + row) * DH + q * 8;
                uint32_t off = sbase + (uint32_t)(SK_BASE + s * 18432 + row * GS + q * 8) * 2;
                cp16(off,            g_khi + src);
                cp16(off + 9216 * 2, g_klo + src);
            }
            {
                int row = f >> 4, q = f & 15;
                size_t src = head + (size_t)row * NSEQ + (size_t)jt_ * 128 + q * 8;
                uint32_t off = sbase + (uint32_t)(SV_BASE + s * 17408 + row * VPS + q * 8) * 2;
                cp16(off,            g_vhi + src);
                cp16(off + 8704 * 2, g_vlo + src);
            }
        }
    };

#pragma unroll
    for (int it = 0; it < 4; it++) {
        int f = tid + 256 * it;
        int row = f >> 3, q = f & 7;
        size_t src = head + (size_t)(row0 + row) * DH + q * 8;
        uint32_t off = sbase + (uint32_t)(row * GS + q * 8) * 2;
        cp16(off,            g_qhi + src);
        cp16(off + 9216 * 2, g_qlo + src);
    }
    load_kv(0, 0);
    CP_COMMIT();
    CP_WAIT(0);
    __syncthreads();

    float oacc[8][4];
#pragma unroll
    for (int i = 0; i < 8; i++)
#pragma unroll
        for (int t = 0; t < 4; t++) oacc[i][t] = 0.f;

    for (int jt = 0; jt < NSEQ / 128; jt++) {
        if (jt < 15) { load_kv(jt + 1, (jt + 1) & 1); CP_COMMIT(); CP_WAIT(1); }
        else         { CP_WAIT(0); }
        __syncthreads();

        const __nv_bfloat16* kh = sma + SK_BASE + (jt & 1) * 18432;
        const __nv_bfloat16* kl = kh + 9216;
        const __nv_bfloat16* vh = sma + SV_BASE + (jt & 1) * 17408;
        const __nv_bfloat16* vl = vh + 8704;

        // ---- S = Q K^T ----
        float sacc[16][4];
#pragma unroll
        for (int i = 0; i < 16; i++)
#pragma unroll
            for (int t = 0; t < 4; t++) sacc[i][t] = 0.f;

#pragma unroll
        for (int ks = 0; ks < 4; ks++) {
            const int k0 = ks * 16;
            uint32_t qfh[4], qfl[4];
            lda_frag(qfh, sma + SQ_H, wid * 16, k0, GS, grp, qd);
            lda_frag(qfl, sma + SQ_L, wid * 16, k0, GS, grp, qd);
#pragma unroll
            for (int g = 0; g < 4; g++) {
                uint32_t bh[4][2], bl[4][2];
#pragma unroll
                for (int j = 0; j < 4; j++) {
                    ldb_frag(bh[j], kh, (g * 4 + j) * 8, k0, GS, grp, qd);
                    ldb_frag(bl[j], kl, (g * 4 + j) * 8, k0, GS, grp, qd);
                }
#pragma unroll
                for (int j = 0; j < 4; j++) mma_bf16(sacc[g * 4 + j], qfh, bh[j]);
#pragma unroll
                for (int j = 0; j < 4; j++) mma_bf16(sacc[g * 4 + j], qfh, bl[j]);
#pragma unroll
                for (int j = 0; j < 4; j++) mma_bf16(sacc[g * 4 + j], qfl, bh[j]);
            }
        }

        // ---- sigmoid + attn store + register P -> PV ----
        float* ab = attn_out
            ? attn_out + ((size_t)bhid * NSEQ + row0 + wid * 16 + grp) * NSEQ
                       + (size_t)jt * 128
            : nullptr;

#pragma unroll
        for (int kc = 0; kc < 8; kc++) {
            float* c0 = sacc[2 * kc];
            float* c1 = sacc[2 * kc + 1];
            float p0 = __fdividef(1.f, 1.f + __expf(-(c0[0] + ATTN_BIAS_F)));
            float p1 = __fdividef(1.f, 1.f + __expf(-(c0[1] + ATTN_BIAS_F)));
            float p2 = __fdividef(1.f, 1.f + __expf(-(c0[2] + ATTN_BIAS_F)));
            float p3 = __fdividef(1.f, 1.f + __expf(-(c0[3] + ATTN_BIAS_F)));
            float p4 = __fdividef(1.f, 1.f + __expf(-(c1[0] + ATTN_BIAS_F)));
            float p5 = __fdividef(1.f, 1.f + __expf(-(c1[1] + ATTN_BIAS_F)));
            float p6 = __fdividef(1.f, 1.f + __expf(-(c1[2] + ATTN_BIAS_F)));
            float p7 = __fdividef(1.f, 1.f + __expf(-(c1[3] + ATTN_BIAS_F)));
            if (ab) {
                float2 w0 = {p0, p1}, w1 = {p2, p3}, w2 = {p4, p5}, w3 = {p6, p7};
                *(float2*)(ab + kc * 16 + 2 * qd) = w0;
                *(float2*)(ab + 8 * NSEQ + kc * 16 + 2 * qd) = w1;
                *(float2*)(ab + kc * 16 + 8 + 2 * qd) = w2;
                *(float2*)(ab + 8 * NSEQ + kc * 16 + 8 + 2 * qd) = w3;
            }
            __nv_bfloat16 h0, h1, h2, h3, h4, h5, h6, h7;
            __nv_bfloat16 l0, l1, l2, l3, l4, l5, l6, l7;
            splitf(p0, h0, l0); splitf(p1, h1, l1); splitf(p2, h2, l2); splitf(p3, h3, l3);
            splitf(p4, h4, l4); splitf(p5, h5, l5); splitf(p6, h6, l6); splitf(p7, h7, l7);
            uint32_t pah[4] = { b2u(h0, h1), b2u(h2, h3), b2u(h4, h5), b2u(h6, h7) };
            uint32_t pal[4] = { b2u(l0, l1), b2u(l2, l3), b2u(l4, l5), b2u(l6, l7) };
#pragma unroll
            for (int g = 0; g < 2; g++) {
                uint32_t vb[4][2], vbl[4][2];
#pragma unroll
                for (int j = 0; j < 4; j++) {
                    ldb_frag(vb[j],  vh, (g * 4 + j) * 8, kc * 16, VPS, grp, qd);
                    ldb_frag(vbl[j], vl, (g * 4 + j) * 8, kc * 16, VPS, grp, qd);
                }
#pragma unroll
                for (int j = 0; j < 4; j++) mma_bf16(oacc[g * 4 + j], pah, vb[j]);
#pragma unroll
                for (int j = 0; j < 4; j++) mma_bf16(oacc[g * 4 + j], pah, vbl[j]);
#pragma unroll
                for (int j = 0; j < 4; j++) mma_bf16(oacc[g * 4 + j], pal, vb[j]);
            }
        }
        __syncthreads();
    }

    // ---- epilogue: O -> fp32 av_out + split bf16 g_avhi/g_avlo ----
    const int r = row0 + wid * 16 + grp;
#pragma unroll
    for (int dt = 0; dt < 8; dt++) {
        int d = dt * 8 + qd * 2;
        size_t base = (((size_t)b * NSEQ + r) * HN + h) * DH + d;
        float2 v0 = {oacc[dt][0], oacc[dt][1]};
        float2 v1 = {oacc[dt][2], oacc[dt][3]};
        *(float2*)(av_out + base) = v0;
        *(float2*)(av_out + base + 8 * (size_t)CDIM) = v1;
        __nv_bfloat16 h0, h1, h2, h3, l0, l1, l2, l3;
        splitf(v0.x, h0, l0); splitf(v0.y, h1, l1);
        splitf(v1.x, h2, l2); splitf(v1.y, h3, l3);
        *(uint32_t*)(g_avhi + base) = b2u(h0, h1);
        *(uint32_t*)(g_avlo + base) = b2u(l0, l1);
        *(uint32_t*)(g_avhi + base + 8 * (size_t)CDIM) = b2u(h2, h3);
        *(uint32_t*)(g_avlo + base + 8 * (size_t)CDIM) = b2u(l2, l3);
    }
}

// ---------------------------------------------------------------------------
// Output projection GEMM: av[4096,1024] @ wproj[1024,1024]^T, pure bf16,
// cp.async double-buffered (reads g_avhi/lo + g_wphi/lo).
// ---------------------------------------------------------------------------
__global__ void __launch_bounds__(256, 1)
tc_gemm_proj(float* __restrict__ Cout)
{
    extern __shared__ __nv_bfloat16 smg[];
    const uint32_t sbase = smem_u32(smg);
    const int tid = threadIdx.x;
    const int wid = tid >> 5, lane = tid & 31;
    const int grp = lane >> 2, qd = lane & 3;
    const int wm = wid >> 2, wn = wid & 3;
    const int row0 = blockIdx.y * 128, col0 = blockIdx.x * 128;

    auto stage_load = [&](int s, int kb) {
#pragma unroll
        for (int it = 0; it < 4; it++) {
            int f = tid + 256 * it;
            int row = f >> 3, q = f & 7;
            size_t asrc = (size_t)(row0 + row) * CDIM + kb * 64 + q * 8;
            size_t bsrc = (size_t)(col0 + row) * CDIM + kb * 64 + q * 8;
            uint32_t off = sbase + (uint32_t)(s * QKV_STAGE + row * GS + q * 8) * 2;
            cp16(off,             g_avhi + asrc);
            cp16(off +  9216 * 2, g_avlo + asrc);
            cp16(off + 18432 * 2, g_wphi + bsrc);
            cp16(off + 27648 * 2, g_wplo + bsrc);
        }
    };

    float acc[4][4][4];
#pragma unroll
    for (int i = 0; i < 4; i++)
#pragma unroll
        for (int j = 0; j < 4; j++)
#pragma unroll
            for (int t = 0; t < 4; t++) acc[i][j][t] = 0.f;

    stage_load(0, 0); CP_COMMIT();

    for (int kb = 0; kb < 16; kb++) {
        if (kb < 15) { stage_load((kb + 1) & 1, kb + 1); CP_COMMIT(); CP_WAIT(1); }
        else         { CP_WAIT(0); }
        __syncthreads();
        gemm_mainloop_step(smg + (kb & 1) * QKV_STAGE, acc, wm, wn, grp, qd);
        __syncthreads();
    }

#pragma unroll
    for (int mt = 0; mt < 4; mt++) {
        int r = row0 + wm * 64 + mt * 16 + grp;
#pragma unroll
        for (int nt = 0; nt < 4; nt++) {
            int cl = col0 + wn * 32 + nt * 8 + qd * 2;
            float* a4 = acc[mt][nt];
            float2 v0 = {a4[0], a4[1]};
            float2 v1 = {a4[2], a4[3]};
            *(float2*)(Cout + (size_t)r * CDIM + cl) = v0;
            *(float2*)(Cout + (size_t)(r + 8) * CDIM + cl) = v1;
        }
    }
}

// ---------------------------------------------------------------------------
// Launch
// ---------------------------------------------------------------------------
extern "C" void kernel_launch(void* const* d_in, const int* in_sizes, int n_in,
                              void* d_out, int out_size)
{
    const float* x     = (const float*)d_in[0];
    const float* wqkv  = (const float*)d_in[1];
    const float* wproj = (const float*)d_in[2];
    float* out = (float*)d_out;

    const size_t SZ_ATTN = (size_t)BSZ * HN * NSEQ * NSEQ;
    const size_t SZ_AV   = (size_t)BSZ * NSEQ * CDIM;
    const bool full = ((size_t)out_size >= SZ_ATTN + 2 * SZ_AV);

    static float* g_av_dev = nullptr;
    static bool attr_done = false;
    if (!attr_done) {
        cudaFuncSetAttribute(tc_gemm_qkv,
                             cudaFuncAttributeMaxDynamicSharedMemorySize, QKV_SMEM);
        cudaFuncSetAttribute(attn_kernel2,
                             cudaFuncAttributeMaxDynamicSharedMemorySize, ATTN_SMEM);
        cudaFuncSetAttribute(tc_gemm_proj,
                             cudaFuncAttributeMaxDynamicSharedMemorySize, QKV_SMEM);
        cudaGetSymbolAddress((void**)&g_av_dev, g_av);
        attr_done = true;
    }

    // 0) split-convert inputs to bf16 hi/lo
    convert_x<<<(int)(NELEM_X / 4 / 256), 256>>>(x);
    convert_w<<<(int)(NELEM_W / 4 / 256), 256>>>(wqkv);
    convert_wp<<<(int)(NELEM_WP / 4 / 256), 256>>>(wproj);

    // 1) QKV projection -> split q/k (row-major) + v (transposed)
    tc_gemm_qkv<<<dim3(3 * CDIM / 128, (BSZ * NSEQ) / 128), 256, QKV_SMEM>>>();

    // 2) Fused sigmoid attention (writes fp32 av + split bf16 av)
    float* attn_dst = full ? out : nullptr;
    float* av_dst   = full ? out + SZ_ATTN : g_av_dev;
    attn_kernel2<<<dim3(NSEQ / 128, BSZ * HN), 256, ATTN_SMEM>>>(attn_dst, av_dst);

    // 3) Output projection (pure bf16 inputs)
    float* proj_dst = full ? out + SZ_ATTN + SZ_AV : out;
    tc_gemm_proj<<<dim3(CDIM / 128, (BSZ * NSEQ) / 128), 256, QKV_SMEM>>>(proj_dst);
}